// round 13
// baseline (speedup 1.0000x reference)
#include <cuda_runtime.h>
#include <cuda_bf16.h>
#include <math.h>
#include <stdint.h>

#define B_ 32
#define T_ 64
#define S_ 64
#define V_ 32000
#define E_ 512
#define H_ 512
#define U_ 1024
#define NH_ 8
#define FEATW 2048
#define NB 128

// ---------------- scratch offsets (floats) ----------------
#define OFF_FEAT   0ull
#define OFF_KEYUP  4194304ull
#define OFF_LOGITS 5242880ull
#define OFF_HT     6291456ull     // hT4 [128 kg][32 b][4]
#define OFF_TMP    6307840ull     // t4 same layout
#define OFF_CTXRT  6340608ull     // c4 [256 kg][32 b][4]
#define OFF_X1ALL  6373376ull     // X1T [64 t][1536 j][32 b]
#define OFF_WFX2   9519104ull
#define OFF_BFX2   11091968ull
#define OFF_WQT    11094016ull
#define OFF_WFT    11356160ull
#define OFF_WO2F   12404736ull
#define OFF_WOPK   12929024ull
#define OFF_BO2    13977600ull
#define OFF_AHL    13978624ull    // [2048,1536] bf16
#define OFF_BHL    15551488ull    // [32000,1536] bf16
#define SCRATCH_FLOATS 40127488ull

__device__ float g_scratch[SCRATCH_FLOATS];
__device__ unsigned g_bar_ctr;

__device__ __forceinline__ uint32_t smem_to_u32(const void* p) {
    uint32_t a;
    asm("{ .reg .u64 t; cvta.to.shared.u64 t, %1; cvt.u32.u64 %0, t; }" : "=r"(a) : "l"(p));
    return a;
}
__device__ __forceinline__ void cp_async16(uint32_t dst, const void* src) {
    asm volatile("cp.async.cg.shared.global [%0], [%1], 16;" :: "r"(dst), "l"(src));
}
#define CP_COMMIT() asm volatile("cp.async.commit_group;" ::: "memory")
#define CP_WAIT(n)  asm volatile("cp.async.wait_group %0;" :: "n"(n) : "memory")
#define SW128(x) ((x) ^ (((x) >> 3) & 0x70))

__device__ __forceinline__ void ldsm_x4(uint32_t& r0, uint32_t& r1, uint32_t& r2, uint32_t& r3,
                                        uint32_t addr) {
    asm volatile("ldmatrix.sync.aligned.m8n8.x4.shared.b16 {%0,%1,%2,%3}, [%4];"
                 : "=r"(r0), "=r"(r1), "=r"(r2), "=r"(r3) : "r"(addr));
}
__device__ __forceinline__ void mma16816(float& c0, float& c1, float& c2, float& c3,
                                         uint32_t a0, uint32_t a1, uint32_t a2, uint32_t a3,
                                         uint32_t b0, uint32_t b1) {
    asm volatile("mma.sync.aligned.m16n8k16.row.col.f32.bf16.bf16.f32 "
                 "{%0,%1,%2,%3}, {%4,%5,%6,%7}, {%8,%9}, {%0,%1,%2,%3};"
                 : "+f"(c0), "+f"(c1), "+f"(c2), "+f"(c3)
                 : "r"(a0), "r"(a1), "r"(a2), "r"(a3), "r"(b0), "r"(b1));
}

// FROZEN barrier (R9/R11 empirical optimum): fence + atomicAdd arrive,
// acquire-spin with nanosleep backoff. Do not modify.
__device__ __forceinline__ void gsync(unsigned& gen) {
    __syncthreads();
    if (threadIdx.x == 0) {
        __threadfence();
        atomicAdd(&g_bar_ctr, 1u);
        unsigned target = (gen + 1u) * (unsigned)NB;
        unsigned v;
        do {
            asm volatile("ld.acquire.gpu.u32 %0, [%1];" : "=r"(v) : "l"(&g_bar_ctr) : "memory");
            if (v < target) __nanosleep(32);
        } while (v < target);
    }
    gen++;
    __syncthreads();
}
__global__ void k_zero() { g_bar_ctr = 0u; }

// ---------------- prep kernels ----------------
__global__ void k_embed(const int* __restrict__ tokens, const float* __restrict__ embed_w,
                        float* __restrict__ feat) {
    int bt = blockIdx.x;
    int tok = tokens[bt];
    const float4* src = reinterpret_cast<const float4*>(embed_w + (size_t)tok * E_);
    float4* dst = reinterpret_cast<float4*>(feat + (size_t)bt * FEATW);
    dst[threadIdx.x] = src[threadIdx.x];
}

__global__ __launch_bounds__(512) void k_bridge(const unsigned char* __restrict__ mask,
                                                const float* __restrict__ enc_out,
                                                const float* __restrict__ Wb,
                                                const float* __restrict__ bb,
                                                float* __restrict__ hT4) {
    int b = blockIdx.x;
    int j = threadIdx.x;
    __shared__ float fn[512];
    __shared__ int sL;
    if (j == 0) {
        int L = S_;
        for (int s = 0; s < S_; s++) if (mask[b * S_ + s]) L--;
        sL = L;
    }
    __syncthreads();
    int L = sL;
    fn[j] = enc_out[((size_t)(L - 1) * B_ + b) * U_ + j];
    __syncthreads();
    float acc = bb[j];
    const float* wr = Wb + (size_t)j * 512;
    for (int k = 0; k < 512; k++) acc += fn[k] * wr[k];
    hT4[(j >> 2) * 128 + b * 4 + (j & 3)] = tanhf(acc);
}

__global__ void k_transpose(const float* __restrict__ W, float* __restrict__ WT, int R, int C) {
    int idx = blockIdx.x * 256 + threadIdx.x;
    if (idx >= R * C) return;
    int n = idx / C, k = idx % C;
    WT[(size_t)k * R + n] = W[idx];
}

__global__ void k_bfx2(const float* __restrict__ g2Wx, const float* __restrict__ bf,
                       const float* __restrict__ g2bx, float* __restrict__ bfx2) {
    int g = blockIdx.x * 256 + threadIdx.x;
    if (g >= 1536) return;
    float a = g2bx[g];
    const float4* w4 = reinterpret_cast<const float4*>(g2Wx + (size_t)g * 1024);
    const float4* b4 = reinterpret_cast<const float4*>(bf);
    for (int k = 0; k < 256; k++) {
        float4 w = w4[k], b = b4[k];
        a += w.x * b.x + w.y * b.y + w.z * b.z + w.w * b.w;
    }
    bfx2[g] = a;
}

__global__ void k_wopack(const float* __restrict__ Wo, const float* __restrict__ Wo2f,
                         float* __restrict__ Wp) {
    int idx = blockIdx.x * 256 + threadIdx.x;
    if (idx >= 512 * 2048) return;
    int e = idx >> 11, c = idx & 2047;
    Wp[idx] = (c < 1024) ? Wo[(size_t)e * 2048 + c] : Wo2f[(size_t)e * 1024 + (c - 1024)];
}
__global__ void k_bo2(const float* __restrict__ Wo, const float* __restrict__ bf,
                      const float* __restrict__ bo, float* __restrict__ bo2) {
    int e = blockIdx.x * 256 + threadIdx.x;
    if (e >= 512) return;
    float a = bo[e];
    const float* w = Wo + (size_t)e * 2048 + 1024;
    for (int m = 0; m < 1024; m++) a += w[m] * bf[m];
    bo2[e] = a;
}

// ---------------- tiled SGEMM-NT with lda ----------------
// mode 0 plain, 1 tanh, 2 keyup remap, 3 X1T remap, 4 tanh + bf16 hi/lo split into Ahl
#define BM 128
#define BN 128
#define BKk 16
__global__ __launch_bounds__(256) void sgemm_nt(const float* __restrict__ A,
                                                const float* __restrict__ Bm,
                                                const float* __restrict__ bias,
                                                float* __restrict__ C,
                                                int M, int N, int K, int lda, int mode) {
    __shared__ float As[BKk][BM];
    __shared__ float Bs[BKk][BN];
    const int bm = blockIdx.y * BM, bn = blockIdx.x * BN;
    const int tid = threadIdx.x;
    const int tm = (tid >> 4) << 3;
    const int tn = (tid & 15) << 3;
    float acc[8][8];
#pragma unroll
    for (int i = 0; i < 8; i++)
#pragma unroll
        for (int j = 0; j < 8; j++) acc[i][j] = 0.f;

    for (int k0 = 0; k0 < K; k0 += BKk) {
#pragma unroll
        for (int i = 0; i < 2; i++) {
            int idx = tid + i * 256;
            int r = idx >> 2, c = (idx & 3) << 2;
            float4 v = *reinterpret_cast<const float4*>(A + (size_t)(bm + r) * lda + k0 + c);
            As[c][r] = v.x; As[c + 1][r] = v.y; As[c + 2][r] = v.z; As[c + 3][r] = v.w;
            float4 w = *reinterpret_cast<const float4*>(Bm + (size_t)(bn + r) * K + k0 + c);
            Bs[c][r] = w.x; Bs[c + 1][r] = w.y; Bs[c + 2][r] = w.z; Bs[c + 3][r] = w.w;
        }
        __syncthreads();
#pragma unroll
        for (int k = 0; k < BKk; k++) {
            float a[8], bb[8];
            *reinterpret_cast<float4*>(&a[0]) = *reinterpret_cast<const float4*>(&As[k][tm]);
            *reinterpret_cast<float4*>(&a[4]) = *reinterpret_cast<const float4*>(&As[k][tm + 4]);
            *reinterpret_cast<float4*>(&bb[0]) = *reinterpret_cast<const float4*>(&Bs[k][tn]);
            *reinterpret_cast<float4*>(&bb[4]) = *reinterpret_cast<const float4*>(&Bs[k][tn + 4]);
#pragma unroll
            for (int i = 0; i < 8; i++)
#pragma unroll
                for (int j = 0; j < 8; j++) acc[i][j] += a[i] * bb[j];
        }
        __syncthreads();
    }
#pragma unroll
    for (int i = 0; i < 8; i++) {
        int m = bm + tm + i;
#pragma unroll
        for (int j = 0; j < 8; j++) {
            int n = bn + tn + j;
            float v = acc[i][j];
            if (bias) v += bias[n];
            if (mode == 1) v = tanhf(v);
            if (mode == 2) {
                int s_ = m >> 5, b_ = m & 31, nh_ = n >> 6, d_ = n & 63;
                C[(((size_t)(b_ * 8 + nh_) * 64) + s_) * 64 + d_] = v;
            } else if (mode == 3) {
                int b_ = m >> 6, t_ = m & 63;
                C[((size_t)t_ * 1536 + n) * 32 + b_] = v;
            } else if (mode == 4) {
                v = tanhf(v);
                __nv_bfloat16* Ahl = reinterpret_cast<__nv_bfloat16*>(C);
                __nv_bfloat16 hi = __float2bfloat16(v);
                __nv_bfloat16 lo = __float2bfloat16(v - __bfloat162float(hi));
                Ahl[(size_t)m * 1536 + n] = hi;
                Ahl[(size_t)m * 1536 + 512 + n] = hi;
                Ahl[(size_t)m * 1536 + 1024 + n] = lo;
            } else {
                C[(size_t)m * N + n] = v;
            }
        }
    }
}

// ---------------- persistent recurrence ----------------
#define PERS_SMEM (51200 * 4)

__global__ __launch_bounds__(512, 1)
void k_persistent(const float* __restrict__ X1T, const float* __restrict__ g1Wh,
                  const float* __restrict__ g1bh,
                  const float* __restrict__ Wfx2, const float* __restrict__ bfx2,
                  const float* __restrict__ g2Wh, const float* __restrict__ g2bh,
                  const float* __restrict__ Wq, const float* __restrict__ bq,
                  const float* __restrict__ Ww, const float* __restrict__ bw,
                  const float* __restrict__ enc_out, const unsigned char* __restrict__ mask,
                  const float* __restrict__ keyup,
                  float* __restrict__ feat, float* __restrict__ hT4,
                  float* __restrict__ t4, float* __restrict__ c4) {
    extern __shared__ float sm[];
    float* W1s  = sm;
    float* W2xs = sm + 12288;
    float* W2hs = sm + 36864;
    float* scr  = sm + 49152;
    const int bid = blockIdx.x, tid = threadIdx.x;
    unsigned gen = 0;
    const int bl = tid & 15, jl = (tid >> 4) & 7, q = tid >> 7;
    const int jb = bid >> 1, bh = bid & 1;
    const int j0 = jb * 8, b0 = bh * 16;

    // stage loop-invariant weights ONCE
    {
        float4* d1 = reinterpret_cast<float4*>(W1s);
        for (int i = tid; i < 3072; i += 512) {
            int jj = i / 384, rem = i % 384, g = rem >> 7, k4 = rem & 127;
            d1[i] = *reinterpret_cast<const float4*>(
                g1Wh + ((size_t)(g * 512 + j0 + jj)) * 512 + k4 * 4);
        }
        float4* d2 = reinterpret_cast<float4*>(W2xs);
        for (int i = tid; i < 6144; i += 512) {
            int jj = i / 768, rem = i % 768, g = rem >> 8, k4 = rem & 255;
            d2[i] = *reinterpret_cast<const float4*>(
                Wfx2 + ((size_t)(g * 512 + j0 + jj)) * 1024 + k4 * 4);
        }
        float4* d3 = reinterpret_cast<float4*>(W2hs);
        for (int i = tid; i < 3072; i += 512) {
            int jj = i / 384, rem = i % 384, g = rem >> 7, k4 = rem & 127;
            d3[i] = *reinterpret_cast<const float4*>(
                g2Wh + ((size_t)(g * 512 + j0 + jj)) * 512 + k4 * 4);
        }
    }
    __syncthreads();

    float h_r, h_z, h_hn;

    for (int t = 0; t < T_; t++) {
        // ============ P1: GRU1 h-gates + combine ============
        float ar = 0.f, az = 0.f, an = 0.f;
        {
            const float4* xp = reinterpret_cast<const float4*>(hT4) + q * 1024 + b0 + bl;
            const float4* wr4 = reinterpret_cast<const float4*>(W1s + (jl * 3 + 0) * 512) + q * 32;
            const float4* wz4 = reinterpret_cast<const float4*>(W1s + (jl * 3 + 1) * 512) + q * 32;
            const float4* wn4 = reinterpret_cast<const float4*>(W1s + (jl * 3 + 2) * 512) + q * 32;
#pragma unroll 8
            for (int kk = 0; kk < 32; kk++) {
                float4 x = __ldcg(xp + kk * 32);
                float4 wr = wr4[kk], wz = wz4[kk], wn = wn4[kk];
                ar += x.x * wr.x + x.y * wr.y + x.z * wr.z + x.w * wr.w;
                az += x.x * wz.x + x.y * wz.y + x.z * wz.z + x.w * wz.w;
                an += x.x * wn.x + x.y * wn.y + x.z * wn.z + x.w * wn.w;
            }
            if (q) {
                int o = (q - 1) * 384 + (jl * 16 + bl) * 3;
                scr[o] = ar; scr[o + 1] = az; scr[o + 2] = an;
            }
        }
        __syncthreads();
        if (q == 0) {
            int o = (jl * 16 + bl) * 3;
            ar += scr[o] + scr[384 + o] + scr[768 + o];
            az += scr[o + 1] + scr[384 + o + 1] + scr[768 + o + 1];
            an += scr[o + 2] + scr[384 + o + 2] + scr[768 + o + 2];
            int j = j0 + jl, b = b0 + bl;
            const float* X1 = X1T + ((size_t)t * 1536) * 32;
            float xr = X1[(size_t)j * 32 + b];
            float xz = X1[(size_t)(512 + j) * 32 + b];
            float xn = X1[(size_t)(1024 + j) * 32 + b];
            float r = 1.f / (1.f + expf(-(xr + g1bh[j] + ar)));
            float z = 1.f / (1.f + expf(-(xz + g1bh[512 + j] + az)));
            float n = tanhf(xn + r * (an + g1bh[1024 + j]));
            float hp = __ldcg(hT4 + (j >> 2) * 128 + b * 4 + (j & 3));
            float o2 = (1.f - z) * n + z * hp;
            t4[(j >> 2) * 128 + b * 4 + (j & 3)] = o2;
        }
        gsync(gen);

        // ============ P2: attention + GRU2 h-part (register carry) ============
        {
            int pr = tid >> 8, tid2 = tid & 255;
            int p = bid * 2 + pr, b = p >> 3, nh = p & 7;
            float* st  = scr + pr * 512;
            float* sq  = scr + 1024 + pr * 64;
            float* sa  = scr + 1152 + pr * 64;
            float* qp  = scr + 1280 + pr * 256;
            float* scp = scr + 1792 + pr * 128;
            for (int i = tid2; i < 512; i += 256)
                st[i] = __ldcg(t4 + (i >> 2) * 128 + b * 4 + (i & 3));
            __syncthreads();
            {
                int d = tid2 & 63, kq = tid2 >> 6;
                const float4* wp = reinterpret_cast<const float4*>(
                    Wq + ((size_t)(nh * 64 + d)) * 512 + kq * 128);
                const float4* sp = reinterpret_cast<const float4*>(st + kq * 128);
                float a = 0.f;
#pragma unroll
                for (int k = 0; k < 32; k++) {
                    float4 w = wp[k], x = sp[k];
                    a += w.x * x.x + w.y * x.y + w.z * x.z + w.w * x.w;
                }
                qp[kq * 64 + d] = a;
            }
            __syncthreads();
            if (tid2 < 64)
                sq[tid2] = bq[nh * 64 + tid2] + qp[tid2] + qp[64 + tid2] + qp[128 + tid2] + qp[192 + tid2];
            __syncthreads();
            if (tid2 < 128) {
                int s = tid2 & 63, dh = tid2 >> 6;
                float a = 0.f;
                const float* kp = keyup + (((size_t)(b * 8 + nh)) * 64 + s) * 64 + dh * 32;
                const float* sqh = sq + dh * 32;
                const float* wwh = Ww + dh * 32;
#pragma unroll 8
                for (int d = 0; d < 32; d++) a += tanhf(sqh[d] + kp[d]) * wwh[d];
                scp[dh * 64 + s] = a;
            }
            __syncthreads();
            if (tid2 < 64) {
                float sc = scp[tid2] + scp[64 + tid2] + bw[0];
                if (mask[b * S_ + tid2]) sc -= 1e9f;
                sa[tid2] = sc;
            }
            __syncthreads();
            if (tid2 < 32) {
                float v0 = sa[tid2], v1 = sa[tid2 + 32];
                float mx = fmaxf(v0, v1);
#pragma unroll
                for (int o = 16; o; o >>= 1) mx = fmaxf(mx, __shfl_xor_sync(0xffffffffu, mx, o));
                float e0 = expf(v0 - mx), e1 = expf(v1 - mx);
                float sum = e0 + e1;
#pragma unroll
                for (int o = 16; o; o >>= 1) sum += __shfl_xor_sync(0xffffffffu, sum, o);
                float inv = 1.f / sum;
                sa[tid2] = e0 * inv;
                sa[tid2 + 32] = e1 * inv;
            }
            __syncthreads();
            if (tid2 < 128) {
                float a = 0.f;
                const float* vp = enc_out + (size_t)b * U_ + nh * 128 + tid2;
#pragma unroll
                for (int s = 0; s < 64; s++) a += sa[s] * vp[(size_t)s * B_ * U_];
                int n = nh * 128 + tid2;
                c4[(n >> 2) * 128 + b * 4 + (n & 3)] = a;
                feat[((size_t)b * T_ + t) * FEATW + 1024 + n] = a;
            }
        }
        // GRU2 h-part overlap
        {
            h_r = 0.f; h_z = 0.f; h_hn = 0.f;
            const float4* xp = reinterpret_cast<const float4*>(t4) + q * 1024 + b0 + bl;
            const float4* wr4 = reinterpret_cast<const float4*>(W2hs + (jl * 3 + 0) * 512) + q * 32;
            const float4* wz4 = reinterpret_cast<const float4*>(W2hs + (jl * 3 + 1) * 512) + q * 32;
            const float4* wn4 = reinterpret_cast<const float4*>(W2hs + (jl * 3 + 2) * 512) + q * 32;
#pragma unroll 8
            for (int kk = 0; kk < 32; kk++) {
                float4 x = __ldcg(xp + kk * 32);
                float4 wr = wr4[kk], wz = wz4[kk], wn = wn4[kk];
                h_r  += x.x * wr.x + x.y * wr.y + x.z * wr.z + x.w * wr.w;
                h_z  += x.x * wz.x + x.y * wz.y + x.z * wz.z + x.w * wz.w;
                h_hn += x.x * wn.x + x.y * wn.y + x.z * wn.z + x.w * wn.w;
            }
        }
        gsync(gen);

        // ============ P3: GRU2 x-part + combine ============
        float a_r = h_r, a_z = h_z, a_xn = 0.f, a_hn = h_hn;
        {
            const float4* xp = reinterpret_cast<const float4*>(c4) + q * 2048 + b0 + bl;
            const float4* wr4 = reinterpret_cast<const float4*>(W2xs + (jl * 3 + 0) * 1024) + q * 64;
            const float4* wz4 = reinterpret_cast<const float4*>(W2xs + (jl * 3 + 1) * 1024) + q * 64;
            const float4* wn4 = reinterpret_cast<const float4*>(W2xs + (jl * 3 + 2) * 1024) + q * 64;
#pragma unroll 8
            for (int kk = 0; kk < 64; kk++) {
                float4 x = __ldcg(xp + kk * 32);
                float4 wr = wr4[kk], wz = wz4[kk], wn = wn4[kk];
                a_r  += x.x * wr.x + x.y * wr.y + x.z * wr.z + x.w * wr.w;
                a_z  += x.x * wz.x + x.y * wz.y + x.z * wz.z + x.w * wz.w;
                a_xn += x.x * wn.x + x.y * wn.y + x.z * wn.z + x.w * wn.w;
            }
            if (q) {
                int o = (q - 1) * 512 + (jl * 16 + bl) * 4;
                scr[o] = a_r; scr[o + 1] = a_z; scr[o + 2] = a_xn; scr[o + 3] = a_hn;
            }
        }
        __syncthreads();
        if (q == 0) {
            int o = (jl * 16 + bl) * 4;
            a_r  += scr[o] + scr[512 + o] + scr[1024 + o];
            a_z  += scr[o + 1] + scr[512 + o + 1] + scr[1024 + o + 1];
            a_xn += scr[o + 2] + scr[512 + o + 2] + scr[1024 + o + 2];
            a_hn += scr[o + 3] + scr[512 + o + 3] + scr[1024 + o + 3];
            int j = j0 + jl, b = b0 + bl, m = b * T_ + t;
            float r = 1.f / (1.f + expf(-(a_r + bfx2[j] + g2bh[j])));
            float z = 1.f / (1.f + expf(-(a_z + bfx2[512 + j] + g2bh[512 + j])));
            float n = tanhf(a_xn + bfx2[1024 + j] + r * (a_hn + g2bh[1024 + j]));
            float hp = __ldcg(t4 + (j >> 2) * 128 + b * 4 + (j & 3));
            float o2 = (1.f - z) * n + z * hp;
            hT4[(j >> 2) * 128 + b * 4 + (j & 3)] = o2;
            feat[(size_t)m * FEATW + 512 + j] = o2;
        }
        gsync(gen);
    }
}

// ============ bf16 hi/lo split for embed_w ============
__global__ void k_convB(const float* __restrict__ W, __nv_bfloat16* __restrict__ Bp) {
    int idx = blockIdx.x * 256 + threadIdx.x;
    if (idx >= 32000 * 128) return;
    int n = idx >> 7, kg = (idx & 127) << 2;
    float4 v = *reinterpret_cast<const float4*>(W + (size_t)n * 512 + kg);
    __nv_bfloat16 h[4], l[4];
    float x[4] = {v.x, v.y, v.z, v.w};
#pragma unroll
    for (int i = 0; i < 4; i++) {
        h[i] = __float2bfloat16(x[i]);
        l[i] = __float2bfloat16(x[i] - __bfloat162float(h[i]));
    }
    __nv_bfloat162* p0 = reinterpret_cast<__nv_bfloat162*>(Bp + (size_t)n * 1536 + kg);
    __nv_bfloat162* p1 = reinterpret_cast<__nv_bfloat162*>(Bp + (size_t)n * 1536 + 512 + kg);
    __nv_bfloat162* p2 = reinterpret_cast<__nv_bfloat162*>(Bp + (size_t)n * 1536 + 1024 + kg);
    p0[0] = __nv_bfloat162(h[0], h[1]); p0[1] = __nv_bfloat162(h[2], h[3]);
    p1[0] = __nv_bfloat162(l[0], l[1]); p1[1] = __nv_bfloat162(l[2], l[3]);
    p2[0] = __nv_bfloat162(h[0], h[1]); p2[1] = __nv_bfloat162(h[2], h[3]);
}

// ============ HMMA bf16 GEMM ============
#define HG_A_BYTES 16384
#define HG_B_BYTES 16384
#define HG_SMEM_TOTAL (2 * (HG_A_BYTES + HG_B_BYTES))

__global__ __launch_bounds__(256, 2)
void mma_gemm_hmma(const __nv_bfloat16* __restrict__ Ap, const __nv_bfloat16* __restrict__ Bp,
                   float* __restrict__ C) {
    extern __shared__ char smemc[];
    uint32_t sb_a = smem_to_u32(smemc);
    uint32_t sb_b = sb_a + 2 * HG_A_BYTES;
    const int tid = threadIdx.x, lane = tid & 31, wid = tid >> 5;
    const int mt = blockIdx.y, nt = blockIdx.x;
    const int m0 = (wid & 3) * 32;
    const int n0 = (wid >> 2) * 64;

    const __nv_bfloat16* Ag = Ap + (size_t)mt * 128 * 1536;
    const __nv_bfloat16* Bg = Bp + (size_t)nt * 128 * 1536;

#define HLOAD(s, buf) { \
    uint32_t ab_ = sb_a + (buf) * HG_A_BYTES; \
    uint32_t bb_ = sb_b + (buf) * HG_B_BYTES; \
    const __nv_bfloat16* As_ = Ag + (s) * 64; \
    const __nv_bfloat16* Bs_ = Bg + (s) * 64; \
    _Pragma("unroll") \
    for (int i_ = 0; i_ < 4; i_++) { int ix_ = tid + i_ * 256; int r_ = ix_ >> 3, c_ = ix_ & 7; \
        cp_async16(ab_ + SW128(r_ * 128 + c_ * 16), As_ + (size_t)r_ * 1536 + c_ * 8); } \
    _Pragma("unroll") \
    for (int i_ = 0; i_ < 4; i_++) { int ix_ = tid + i_ * 256; int r_ = ix_ >> 3, c_ = ix_ & 7; \
        cp_async16(bb_ + SW128(r_ * 128 + c_ * 16), Bs_ + (size_t)r_ * 1536 + c_ * 8); } \
    CP_COMMIT(); }

    float acc[2][8][4];
#pragma unroll
    for (int i = 0; i < 2; i++)
#pragma unroll
        for (int j = 0; j < 8; j++)
#pragma unroll
            for (int v = 0; v < 4; v++) acc[i][j][v] = 0.f;

    HLOAD(0, 0);
    HLOAD(1, 1);

    const int a_row_off = ((lane >> 3) & 1) * 8 + (lane & 7);
    const int a_kb_off  = ((lane >> 4) & 1) * 16;
    const int b_row_off = ((lane >> 4) & 1) * 8 + (lane & 7);
    const int b_kb_off  = ((lane >> 3) & 1) * 16;

    for (int s = 0; s < 24; s++) {
        int buf = s & 1;
        CP_WAIT(1);
        __syncthreads();
        uint32_t abase = sb_a + buf * HG_A_BYTES;
        uint32_t bbase = sb_b + buf * HG_B_BYTES;
#pragma unroll
        for (int kk = 0; kk < 4; kk++) {
            uint32_t a[2][4];
#pragma unroll
            for (int mi = 0; mi < 2; mi++) {
                int row = m0 + mi * 16 + a_row_off;
                int kb = kk * 32 + a_kb_off;
                ldsm_x4(a[mi][0], a[mi][1], a[mi][2], a[mi][3], abase + SW128(row * 128 + kb));
            }
            uint32_t bfr[4][4];
#pragma unroll
            for (int ng = 0; ng < 4; ng++) {
                int row = n0 + ng * 16 + b_row_off;
                int kb = kk * 32 + b_kb_off;
                ldsm_x4(bfr[ng][0], bfr[ng][1], bfr[ng][2], bfr[ng][3], bbase + SW128(row * 128 + kb));
            }
#pragma unroll
            for (int mi = 0; mi < 2; mi++)
#pragma unroll
                for (int nj = 0; nj < 8; nj++) {
                    uint32_t b0 = bfr[nj >> 1][(nj & 1) * 2];
                    uint32_t b1 = bfr[nj >> 1][(nj & 1) * 2 + 1];
                    mma16816(acc[mi][nj][0], acc[mi][nj][1], acc[mi][nj][2], acc[mi][nj][3],
                             a[mi][0], a[mi][1], a[mi][2], a[mi][3], b0, b1);
                }
        }
        __syncthreads();
        if (s + 2 < 24) HLOAD(s + 2, buf);
    }

    int gr = mt * 128 + m0 + (lane >> 2);
    int gc = nt * 128 + n0 + (lane & 3) * 2;
#pragma unroll
    for (int mi = 0; mi < 2; mi++) {
#pragma unroll
        for (int nj = 0; nj < 8; nj++) {
            float* p0 = C + (size_t)(gr + mi * 16) * V_ + gc + nj * 8;
            float* p1 = C + (size_t)(gr + mi * 16 + 8) * V_ + gc + nj * 8;
            *reinterpret_cast<float2*>(p0) = make_float2(acc[mi][nj][0], acc[mi][nj][1]);
            *reinterpret_cast<float2*>(p1) = make_float2(acc[mi][nj][2], acc[mi][nj][3]);
        }
    }
}

// ---------------- host orchestration ----------------
extern "C" void kernel_launch(void* const* d_in, const int* in_sizes, int n_in,
                              void* d_out, int out_size) {
    const int*   tokens  = (const int*)d_in[0];
    const unsigned char* enc_mask = (const unsigned char*)d_in[1];
    const float* enc_out = (const float*)d_in[2];
    const float* embed_w = (const float*)d_in[3];
    const float* g1Wx = (const float*)d_in[4];
    const float* g1Wh = (const float*)d_in[5];
    const float* g1bx = (const float*)d_in[6];
    const float* g1bh = (const float*)d_in[7];
    const float* g2Wx = (const float*)d_in[8];
    const float* g2Wh = (const float*)d_in[9];
    const float* g2bx = (const float*)d_in[10];
    const float* g2bh = (const float*)d_in[11];
    const float* brW  = (const float*)d_in[12];
    const float* brB  = (const float*)d_in[13];
    const float* Wk   = (const float*)d_in[14];
    const float* bk   = (const float*)d_in[15];
    const float* Wq   = (const float*)d_in[16];
    const float* bq   = (const float*)d_in[17];
    const float* Ww   = (const float*)d_in[18];
    const float* bw   = (const float*)d_in[19];
    const float* Wf   = (const float*)d_in[20];
    const float* bf   = (const float*)d_in[21];
    const float* Wo   = (const float*)d_in[22];
    const float* bo   = (const float*)d_in[23];
    float* out = (float*)d_out;

    float* S = nullptr;
    cudaGetSymbolAddress((void**)&S, g_scratch);
    float* feat    = S + OFF_FEAT;
    float* keyup   = S + OFF_KEYUP;
    float* hT4     = S + OFF_HT;
    float* t4      = S + OFF_TMP;
    float* c4      = S + OFF_CTXRT;
    float* X1T     = S + OFF_X1ALL;
    float* Wfx2    = S + OFF_WFX2;
    float* bfx2    = S + OFF_BFX2;
    float* WfT     = S + OFF_WFT;
    float* Wo2f    = S + OFF_WO2F;
    float* Wopk    = S + OFF_WOPK;
    float* bo2     = S + OFF_BO2;
    __nv_bfloat16* Ahl = (__nv_bfloat16*)(S + OFF_AHL);
    __nv_bfloat16* Bhl = (__nv_bfloat16*)(S + OFF_BHL);

    // ---- prep ----
    k_embed<<<B_ * T_, 128>>>(tokens, embed_w, feat);
    k_bridge<<<B_, 512>>>(enc_mask, enc_out, brW, brB, hT4);
    k_transpose<<<(1024 * 1024 + 255) / 256, 256>>>(Wf, WfT, 1024, 1024);
    k_bfx2<<<6, 256>>>(g2Wx, bf, g2bx, bfx2);
    k_bo2<<<2, 256>>>(Wo, bf, bo, bo2);
    k_convB<<<(32000 * 128 + 255) / 256, 256>>>(embed_w, Bhl);
    {   // keyup = enc @ Wk^T + bk
        dim3 g(512 / BN, 2048 / BM);
        sgemm_nt<<<g, 256>>>(enc_out, Wk, bk, keyup, 2048, 512, 1024, 1024, 2);
    }
    {   // X1T = emb @ g1Wx^T + g1bx, stored [t][j][b]
        dim3 g(1536 / BN, 2048 / BM);
        sgemm_nt<<<g, 256>>>(feat, g1Wx, g1bx, X1T, 2048, 1536, 512, 2048, 3);
    }
    {   // Wfx2 = g2Wx (x) Wf
        dim3 g(1024 / BN, 1536 / BM);
        sgemm_nt<<<g, 256>>>(g2Wx, WfT, nullptr, Wfx2, 1536, 1024, 1024, 1024, 0);
    }
    {   // Wo2f[e][n] = sum_m Wo[e][1024+m] Wf[m][n]
        dim3 g(1024 / BN, 512 / BM);
        sgemm_nt<<<g, 256>>>(Wo + 1024, WfT, nullptr, Wo2f, 512, 1024, 1024, 2048, 0);
    }
    k_wopack<<<(512 * 2048 + 255) / 256, 256>>>(Wo, Wo2f, Wopk);

    // ---- persistent recurrence ----
    k_zero<<<1, 1>>>();
    cudaFuncSetAttribute(k_persistent, cudaFuncAttributeMaxDynamicSharedMemorySize, PERS_SMEM);
    k_persistent<<<NB, 512, PERS_SMEM>>>(X1T, g1Wh, g1bh, Wfx2, bfx2, g2Wh, g2bh,
                                         Wq, bq, Ww, bw,
                                         enc_out, enc_mask, keyup,
                                         feat, hT4, t4, c4);

    {   // logits = tanh(feat_pack @ Wopk^T + bo2) -> Ahl hi/lo directly (mode 4)
        dim3 g(512 / BN, 2048 / BM);
        sgemm_nt<<<g, 256>>>(feat, Wopk, bo2, (float*)Ahl, 2048, 512, 2048, 2048, 4);
    }
    cudaFuncSetAttribute(mma_gemm_hmma, cudaFuncAttributeMaxDynamicSharedMemorySize, HG_SMEM_TOTAL);
    {
        dim3 g(V_ / 128, 2048 / 128);
        mma_gemm_hmma<<<g, 256, HG_SMEM_TOTAL>>>(Ahl, Bhl, out);
    }
}

// round 14
// speedup vs baseline: 1.1776x; 1.1776x over previous
#include <cuda_runtime.h>
#include <cuda_bf16.h>
#include <math.h>
#include <stdint.h>

#define B_ 32
#define T_ 64
#define S_ 64
#define V_ 32000
#define E_ 512
#define H_ 512
#define U_ 1024
#define NH_ 8
#define FEATW 2048
#define NB 128

// ---------------- scratch offsets (floats) ----------------
#define OFF_FEAT   0ull
#define OFF_KEYUP  4194304ull
#define OFF_LOGITS 5242880ull
#define OFF_HT     6291456ull     // hT4 [128 kg][32 b][4]
#define OFF_TMP    6307840ull     // t4 same layout
#define OFF_CTXRT  6340608ull     // c4 [256 kg][32 b][4]
#define OFF_X1ALL  6373376ull     // X1T [64 t][1536 j][32 b]
#define OFF_WFX2   9519104ull
#define OFF_BFX2   11091968ull
#define OFF_WQT    11094016ull
#define OFF_WFT    11356160ull
#define OFF_WO2F   12404736ull
#define OFF_WOPK   12929024ull
#define OFF_BO2    13977600ull
#define OFF_AHL    13978624ull    // [2048,1536] bf16
#define OFF_BHL    15551488ull    // [32000,1536] bf16
#define SCRATCH_FLOATS 40127488ull

__device__ float g_scratch[SCRATCH_FLOATS];
__device__ unsigned g_bar_ctr;

__device__ __forceinline__ uint32_t smem_to_u32(const void* p) {
    uint32_t a;
    asm("{ .reg .u64 t; cvta.to.shared.u64 t, %1; cvt.u32.u64 %0, t; }" : "=r"(a) : "l"(p));
    return a;
}
__device__ __forceinline__ void cp_async16(uint32_t dst, const void* src) {
    asm volatile("cp.async.cg.shared.global [%0], [%1], 16;" :: "r"(dst), "l"(src));
}
#define CP_COMMIT() asm volatile("cp.async.commit_group;" ::: "memory")
#define CP_WAIT(n)  asm volatile("cp.async.wait_group %0;" :: "n"(n) : "memory")
#define SW128(x) ((x) ^ (((x) >> 3) & 0x70))

__device__ __forceinline__ void ldsm_x4(uint32_t& r0, uint32_t& r1, uint32_t& r2, uint32_t& r3,
                                        uint32_t addr) {
    asm volatile("ldmatrix.sync.aligned.m8n8.x4.shared.b16 {%0,%1,%2,%3}, [%4];"
                 : "=r"(r0), "=r"(r1), "=r"(r2), "=r"(r3) : "r"(addr));
}
__device__ __forceinline__ void mma16816(float& c0, float& c1, float& c2, float& c3,
                                         uint32_t a0, uint32_t a1, uint32_t a2, uint32_t a3,
                                         uint32_t b0, uint32_t b1) {
    asm volatile("mma.sync.aligned.m16n8k16.row.col.f32.bf16.bf16.f32 "
                 "{%0,%1,%2,%3}, {%4,%5,%6,%7}, {%8,%9}, {%0,%1,%2,%3};"
                 : "+f"(c0), "+f"(c1), "+f"(c2), "+f"(c3)
                 : "r"(a0), "r"(a1), "r"(a2), "r"(a3), "r"(b0), "r"(b1));
}

// FROZEN barrier (R9/R11 empirical optimum). Do not modify.
__device__ __forceinline__ void gsync(unsigned& gen) {
    __syncthreads();
    if (threadIdx.x == 0) {
        __threadfence();
        atomicAdd(&g_bar_ctr, 1u);
        unsigned target = (gen + 1u) * (unsigned)NB;
        unsigned v;
        do {
            asm volatile("ld.acquire.gpu.u32 %0, [%1];" : "=r"(v) : "l"(&g_bar_ctr) : "memory");
            if (v < target) __nanosleep(32);
        } while (v < target);
    }
    gen++;
    __syncthreads();
}
__global__ void k_zero() { g_bar_ctr = 0u; }

// ---------------- prep kernels ----------------
__global__ void k_embed(const int* __restrict__ tokens, const float* __restrict__ embed_w,
                        float* __restrict__ feat) {
    int bt = blockIdx.x;
    int tok = tokens[bt];
    const float4* src = reinterpret_cast<const float4*>(embed_w + (size_t)tok * E_);
    float4* dst = reinterpret_cast<float4*>(feat + (size_t)bt * FEATW);
    dst[threadIdx.x] = src[threadIdx.x];
}

__global__ __launch_bounds__(512) void k_bridge(const unsigned char* __restrict__ mask,
                                                const float* __restrict__ enc_out,
                                                const float* __restrict__ Wb,
                                                const float* __restrict__ bb,
                                                float* __restrict__ hT4) {
    int b = blockIdx.x;
    int j = threadIdx.x;
    __shared__ float fn[512];
    __shared__ int sL;
    if (j == 0) {
        int L = S_;
        for (int s = 0; s < S_; s++) if (mask[b * S_ + s]) L--;
        sL = L;
    }
    __syncthreads();
    int L = sL;
    fn[j] = enc_out[((size_t)(L - 1) * B_ + b) * U_ + j];
    __syncthreads();
    float acc = bb[j];
    const float* wr = Wb + (size_t)j * 512;
    for (int k = 0; k < 512; k++) acc += fn[k] * wr[k];
    hT4[(j >> 2) * 128 + b * 4 + (j & 3)] = tanhf(acc);
}

__global__ void k_transpose(const float* __restrict__ W, float* __restrict__ WT, int R, int C) {
    int idx = blockIdx.x * 256 + threadIdx.x;
    if (idx >= R * C) return;
    int n = idx / C, k = idx % C;
    WT[(size_t)k * R + n] = W[idx];
}

__global__ void k_bfx2(const float* __restrict__ g2Wx, const float* __restrict__ bf,
                       const float* __restrict__ g2bx, float* __restrict__ bfx2) {
    int g = blockIdx.x * 256 + threadIdx.x;
    if (g >= 1536) return;
    float a = g2bx[g];
    const float4* w4 = reinterpret_cast<const float4*>(g2Wx + (size_t)g * 1024);
    const float4* b4 = reinterpret_cast<const float4*>(bf);
    for (int k = 0; k < 256; k++) {
        float4 w = w4[k], b = b4[k];
        a += w.x * b.x + w.y * b.y + w.z * b.z + w.w * b.w;
    }
    bfx2[g] = a;
}

__global__ void k_wopack(const float* __restrict__ Wo, const float* __restrict__ Wo2f,
                         float* __restrict__ Wp) {
    int idx = blockIdx.x * 256 + threadIdx.x;
    if (idx >= 512 * 2048) return;
    int e = idx >> 11, c = idx & 2047;
    Wp[idx] = (c < 1024) ? Wo[(size_t)e * 2048 + c] : Wo2f[(size_t)e * 1024 + (c - 1024)];
}
__global__ void k_bo2(const float* __restrict__ Wo, const float* __restrict__ bf,
                      const float* __restrict__ bo, float* __restrict__ bo2) {
    int e = blockIdx.x * 256 + threadIdx.x;
    if (e >= 512) return;
    float a = bo[e];
    const float* w = Wo + (size_t)e * 2048 + 1024;
    for (int m = 0; m < 1024; m++) a += w[m] * bf[m];
    bo2[e] = a;
}

// ---------------- tiled SGEMM-NT with lda ----------------
// mode 0 plain, 1 tanh, 2 keyup remap, 3 X1T remap, 4 tanh + bf16 hi/lo split into Ahl
#define BM 128
#define BN 128
#define BKk 16
__global__ __launch_bounds__(256) void sgemm_nt(const float* __restrict__ A,
                                                const float* __restrict__ Bm,
                                                const float* __restrict__ bias,
                                                float* __restrict__ C,
                                                int M, int N, int K, int lda, int mode) {
    __shared__ float As[BKk][BM];
    __shared__ float Bs[BKk][BN];
    const int bm = blockIdx.y * BM, bn = blockIdx.x * BN;
    const int tid = threadIdx.x;
    const int tm = (tid >> 4) << 3;
    const int tn = (tid & 15) << 3;
    float acc[8][8];
#pragma unroll
    for (int i = 0; i < 8; i++)
#pragma unroll
        for (int j = 0; j < 8; j++) acc[i][j] = 0.f;

    for (int k0 = 0; k0 < K; k0 += BKk) {
#pragma unroll
        for (int i = 0; i < 2; i++) {
            int idx = tid + i * 256;
            int r = idx >> 2, c = (idx & 3) << 2;
            float4 v = *reinterpret_cast<const float4*>(A + (size_t)(bm + r) * lda + k0 + c);
            As[c][r] = v.x; As[c + 1][r] = v.y; As[c + 2][r] = v.z; As[c + 3][r] = v.w;
            float4 w = *reinterpret_cast<const float4*>(Bm + (size_t)(bn + r) * K + k0 + c);
            Bs[c][r] = w.x; Bs[c + 1][r] = w.y; Bs[c + 2][r] = w.z; Bs[c + 3][r] = w.w;
        }
        __syncthreads();
#pragma unroll
        for (int k = 0; k < BKk; k++) {
            float a[8], bb[8];
            *reinterpret_cast<float4*>(&a[0]) = *reinterpret_cast<const float4*>(&As[k][tm]);
            *reinterpret_cast<float4*>(&a[4]) = *reinterpret_cast<const float4*>(&As[k][tm + 4]);
            *reinterpret_cast<float4*>(&bb[0]) = *reinterpret_cast<const float4*>(&Bs[k][tn]);
            *reinterpret_cast<float4*>(&bb[4]) = *reinterpret_cast<const float4*>(&Bs[k][tn + 4]);
#pragma unroll
            for (int i = 0; i < 8; i++)
#pragma unroll
                for (int j = 0; j < 8; j++) acc[i][j] += a[i] * bb[j];
        }
        __syncthreads();
    }
#pragma unroll
    for (int i = 0; i < 8; i++) {
        int m = bm + tm + i;
#pragma unroll
        for (int j = 0; j < 8; j++) {
            int n = bn + tn + j;
            float v = acc[i][j];
            if (bias) v += bias[n];
            if (mode == 1) v = tanhf(v);
            if (mode == 2) {
                int s_ = m >> 5, b_ = m & 31, nh_ = n >> 6, d_ = n & 63;
                C[(((size_t)(b_ * 8 + nh_) * 64) + s_) * 64 + d_] = v;
            } else if (mode == 3) {
                int b_ = m >> 6, t_ = m & 63;
                C[((size_t)t_ * 1536 + n) * 32 + b_] = v;
            } else if (mode == 4) {
                v = tanhf(v);
                __nv_bfloat16* Ahl = reinterpret_cast<__nv_bfloat16*>(C);
                __nv_bfloat16 hi = __float2bfloat16(v);
                __nv_bfloat16 lo = __float2bfloat16(v - __bfloat162float(hi));
                Ahl[(size_t)m * 1536 + n] = hi;
                Ahl[(size_t)m * 1536 + 512 + n] = hi;
                Ahl[(size_t)m * 1536 + 1024 + n] = lo;
            } else {
                C[(size_t)m * N + n] = v;
            }
        }
    }
}

// ---------------- persistent recurrence ----------------
#define PERS_SMEM (51200 * 4)

__global__ __launch_bounds__(512, 1)
void k_persistent(const float* __restrict__ X1T, const float* __restrict__ g1Wh,
                  const float* __restrict__ g1bh,
                  const float* __restrict__ Wfx2, const float* __restrict__ bfx2,
                  const float* __restrict__ g2Wh, const float* __restrict__ g2bh,
                  const float* __restrict__ WqT, const float* __restrict__ bq,
                  const float* __restrict__ Ww, const float* __restrict__ bw,
                  const float* __restrict__ enc_out, const unsigned char* __restrict__ mask,
                  const float* __restrict__ keyup,
                  float* __restrict__ feat, float* __restrict__ hT4,
                  float* __restrict__ t4, float* __restrict__ c4) {
    extern __shared__ float sm[];
    float* W1s  = sm;
    float* W2xs = sm + 12288;
    float* W2hs = sm + 36864;
    float* scr  = sm + 49152;
    const int bid = blockIdx.x, tid = threadIdx.x;
    unsigned gen = 0;
    const int bl = tid & 15, jl = (tid >> 4) & 7, q = tid >> 7;
    const int jb = bid >> 1, bh = bid & 1;
    const int j0 = jb * 8, b0 = bh * 16;

    // stage loop-invariant weights ONCE
    {
        float4* d1 = reinterpret_cast<float4*>(W1s);
        for (int i = tid; i < 3072; i += 512) {
            int jj = i / 384, rem = i % 384, g = rem >> 7, k4 = rem & 127;
            d1[i] = *reinterpret_cast<const float4*>(
                g1Wh + ((size_t)(g * 512 + j0 + jj)) * 512 + k4 * 4);
        }
        float4* d2 = reinterpret_cast<float4*>(W2xs);
        for (int i = tid; i < 6144; i += 512) {
            int jj = i / 768, rem = i % 768, g = rem >> 8, k4 = rem & 255;
            d2[i] = *reinterpret_cast<const float4*>(
                Wfx2 + ((size_t)(g * 512 + j0 + jj)) * 1024 + k4 * 4);
        }
        float4* d3 = reinterpret_cast<float4*>(W2hs);
        for (int i = tid; i < 3072; i += 512) {
            int jj = i / 384, rem = i % 384, g = rem >> 7, k4 = rem & 127;
            d3[i] = *reinterpret_cast<const float4*>(
                g2Wh + ((size_t)(g * 512 + j0 + jj)) * 512 + k4 * 4);
        }
    }
    __syncthreads();

    float h_r, h_z, h_hn;
    // register carries for the combine critical path (valid on q==0 threads)
    float h_prev = 0.f, t_prev = 0.f;
    if (q == 0) {
        int j = j0 + jl, b = b0 + bl;
        h_prev = hT4[(j >> 2) * 128 + b * 4 + (j & 3)];
    }

    for (int t = 0; t < T_; t++) {
        // ============ P1: GRU1 h-gates + combine ============
        float ar = 0.f, az = 0.f, an = 0.f;
        float xr, xz, xn;
        if (q == 0) {   // hoist streamed X1 loads to overlap the dot product
            int j = j0 + jl, b = b0 + bl;
            const float* X1 = X1T + ((size_t)t * 1536) * 32;
            xr = __ldcg(X1 + (size_t)j * 32 + b);
            xz = __ldcg(X1 + (size_t)(512 + j) * 32 + b);
            xn = __ldcg(X1 + (size_t)(1024 + j) * 32 + b);
        }
        {
            const float4* xp = reinterpret_cast<const float4*>(hT4) + q * 1024 + b0 + bl;
            const float4* wr4 = reinterpret_cast<const float4*>(W1s + (jl * 3 + 0) * 512) + q * 32;
            const float4* wz4 = reinterpret_cast<const float4*>(W1s + (jl * 3 + 1) * 512) + q * 32;
            const float4* wn4 = reinterpret_cast<const float4*>(W1s + (jl * 3 + 2) * 512) + q * 32;
#pragma unroll 8
            for (int kk = 0; kk < 32; kk++) {
                float4 x = __ldcg(xp + kk * 32);
                float4 wr = wr4[kk], wz = wz4[kk], wn = wn4[kk];
                ar += x.x * wr.x + x.y * wr.y + x.z * wr.z + x.w * wr.w;
                az += x.x * wz.x + x.y * wz.y + x.z * wz.z + x.w * wz.w;
                an += x.x * wn.x + x.y * wn.y + x.z * wn.z + x.w * wn.w;
            }
            if (q) {
                int o = (q - 1) * 384 + (jl * 16 + bl) * 3;
                scr[o] = ar; scr[o + 1] = az; scr[o + 2] = an;
            }
        }
        __syncthreads();
        if (q == 0) {
            int o = (jl * 16 + bl) * 3;
            ar += scr[o] + scr[384 + o] + scr[768 + o];
            az += scr[o + 1] + scr[384 + o + 1] + scr[768 + o + 1];
            an += scr[o + 2] + scr[384 + o + 2] + scr[768 + o + 2];
            int j = j0 + jl, b = b0 + bl;
            float r = 1.f / (1.f + expf(-(xr + g1bh[j] + ar)));
            float z = 1.f / (1.f + expf(-(xz + g1bh[512 + j] + az)));
            float n = tanhf(xn + r * (an + g1bh[1024 + j]));
            float o2 = (1.f - z) * n + z * h_prev;
            t_prev = o2;
            t4[(j >> 2) * 128 + b * 4 + (j & 3)] = o2;
        }
        gsync(gen);

        // ============ P2: attention + GRU2 h-part (register carry) ============
        {
            int pr = tid >> 8, tid2 = tid & 255;
            int p = bid * 2 + pr, b = p >> 3, nh = p & 7;
            float* st  = scr + pr * 512;
            float* sq  = scr + 1024 + pr * 64;
            float* sa  = scr + 1152 + pr * 64;
            float* qp  = scr + 1280 + pr * 256;
            float* scp = scr + 1792 + pr * 128;
            for (int i = tid2; i < 512; i += 256)
                st[i] = __ldcg(t4 + (i >> 2) * 128 + b * 4 + (i & 3));
            __syncthreads();
            {
                int d = tid2 & 63, kq = tid2 >> 6;
                float a = 0.f;
                const float* wp = WqT + nh * 64 + d;
                int k0 = kq * 128;
#pragma unroll 16
                for (int k = k0; k < k0 + 128; k++) a += st[k] * wp[(size_t)k * 512];
                qp[kq * 64 + d] = a;
            }
            __syncthreads();
            if (tid2 < 64)
                sq[tid2] = bq[nh * 64 + tid2] + qp[tid2] + qp[64 + tid2] + qp[128 + tid2] + qp[192 + tid2];
            __syncthreads();
            if (tid2 < 128) {
                int s = tid2 & 63, dh = tid2 >> 6;
                float a = 0.f;
                const float* kp = keyup + (((size_t)(b * 8 + nh)) * 64 + s) * 64 + dh * 32;
                const float* sqh = sq + dh * 32;
                const float* wwh = Ww + dh * 32;
#pragma unroll 8
                for (int d = 0; d < 32; d++) a += tanhf(sqh[d] + kp[d]) * wwh[d];
                scp[dh * 64 + s] = a;
            }
            __syncthreads();
            if (tid2 < 64) {
                float sc = scp[tid2] + scp[64 + tid2] + bw[0];
                if (mask[b * S_ + tid2]) sc -= 1e9f;
                sa[tid2] = sc;
            }
            __syncthreads();
            if (tid2 < 32) {
                float v0 = sa[tid2], v1 = sa[tid2 + 32];
                float mx = fmaxf(v0, v1);
#pragma unroll
                for (int o = 16; o; o >>= 1) mx = fmaxf(mx, __shfl_xor_sync(0xffffffffu, mx, o));
                float e0 = expf(v0 - mx), e1 = expf(v1 - mx);
                float sum = e0 + e1;
#pragma unroll
                for (int o = 16; o; o >>= 1) sum += __shfl_xor_sync(0xffffffffu, sum, o);
                float inv = 1.f / sum;
                sa[tid2] = e0 * inv;
                sa[tid2 + 32] = e1 * inv;
            }
            __syncthreads();
            if (tid2 < 128) {
                float a = 0.f;
                const float* vp = enc_out + (size_t)b * U_ + nh * 128 + tid2;
#pragma unroll
                for (int s = 0; s < 64; s++) a += sa[s] * vp[(size_t)s * B_ * U_];
                int n = nh * 128 + tid2;
                c4[(n >> 2) * 128 + b * 4 + (n & 3)] = a;
                feat[((size_t)b * T_ + t) * FEATW + 1024 + n] = a;
            }
        }
        // GRU2 h-part overlap
        {
            h_r = 0.f; h_z = 0.f; h_hn = 0.f;
            const float4* xp = reinterpret_cast<const float4*>(t4) + q * 1024 + b0 + bl;
            const float4* wr4 = reinterpret_cast<const float4*>(W2hs + (jl * 3 + 0) * 512) + q * 32;
            const float4* wz4 = reinterpret_cast<const float4*>(W2hs + (jl * 3 + 1) * 512) + q * 32;
            const float4* wn4 = reinterpret_cast<const float4*>(W2hs + (jl * 3 + 2) * 512) + q * 32;
#pragma unroll 8
            for (int kk = 0; kk < 32; kk++) {
                float4 x = __ldcg(xp + kk * 32);
                float4 wr = wr4[kk], wz = wz4[kk], wn = wn4[kk];
                h_r  += x.x * wr.x + x.y * wr.y + x.z * wr.z + x.w * wr.w;
                h_z  += x.x * wz.x + x.y * wz.y + x.z * wz.z + x.w * wz.w;
                h_hn += x.x * wn.x + x.y * wn.y + x.z * wn.z + x.w * wn.w;
            }
        }
        gsync(gen);

        // ============ P3: GRU2 x-part + combine ============
        float a_r = h_r, a_z = h_z, a_xn = 0.f, a_hn = h_hn;
        {
            const float4* xp = reinterpret_cast<const float4*>(c4) + q * 2048 + b0 + bl;
            const float4* wr4 = reinterpret_cast<const float4*>(W2xs + (jl * 3 + 0) * 1024) + q * 64;
            const float4* wz4 = reinterpret_cast<const float4*>(W2xs + (jl * 3 + 1) * 1024) + q * 64;
            const float4* wn4 = reinterpret_cast<const float4*>(W2xs + (jl * 3 + 2) * 1024) + q * 64;
#pragma unroll 8
            for (int kk = 0; kk < 64; kk++) {
                float4 x = __ldcg(xp + kk * 32);
                float4 wr = wr4[kk], wz = wz4[kk], wn = wn4[kk];
                a_r  += x.x * wr.x + x.y * wr.y + x.z * wr.z + x.w * wr.w;
                a_z  += x.x * wz.x + x.y * wz.y + x.z * wz.z + x.w * wz.w;
                a_xn += x.x * wn.x + x.y * wn.y + x.z * wn.z + x.w * wn.w;
            }
            if (q) {
                int o = (q - 1) * 512 + (jl * 16 + bl) * 4;
                scr[o] = a_r; scr[o + 1] = a_z; scr[o + 2] = a_xn; scr[o + 3] = a_hn;
            }
        }
        __syncthreads();
        if (q == 0) {
            int o = (jl * 16 + bl) * 4;
            a_r  += scr[o] + scr[512 + o] + scr[1024 + o];
            a_z  += scr[o + 1] + scr[512 + o + 1] + scr[1024 + o + 1];
            a_xn += scr[o + 2] + scr[512 + o + 2] + scr[1024 + o + 2];
            a_hn += scr[o + 3] + scr[512 + o + 3] + scr[1024 + o + 3];
            int j = j0 + jl, b = b0 + bl, m = b * T_ + t;
            float r = 1.f / (1.f + expf(-(a_r + bfx2[j] + g2bh[j])));
            float z = 1.f / (1.f + expf(-(a_z + bfx2[512 + j] + g2bh[512 + j])));
            float n = tanhf(a_xn + bfx2[1024 + j] + r * (a_hn + g2bh[1024 + j]));
            float o2 = (1.f - z) * n + z * t_prev;
            h_prev = o2;
            hT4[(j >> 2) * 128 + b * 4 + (j & 3)] = o2;
            feat[(size_t)m * FEATW + 512 + j] = o2;
        }
        gsync(gen);
    }
}

// ============ bf16 hi/lo split for embed_w ============
__global__ void k_convB(const float* __restrict__ W, __nv_bfloat16* __restrict__ Bp) {
    int idx = blockIdx.x * 256 + threadIdx.x;
    if (idx >= 32000 * 128) return;
    int n = idx >> 7, kg = (idx & 127) << 2;
    float4 v = *reinterpret_cast<const float4*>(W + (size_t)n * 512 + kg);
    __nv_bfloat16 h[4], l[4];
    float x[4] = {v.x, v.y, v.z, v.w};
#pragma unroll
    for (int i = 0; i < 4; i++) {
        h[i] = __float2bfloat16(x[i]);
        l[i] = __float2bfloat16(x[i] - __bfloat162float(h[i]));
    }
    __nv_bfloat162* p0 = reinterpret_cast<__nv_bfloat162*>(Bp + (size_t)n * 1536 + kg);
    __nv_bfloat162* p1 = reinterpret_cast<__nv_bfloat162*>(Bp + (size_t)n * 1536 + 512 + kg);
    __nv_bfloat162* p2 = reinterpret_cast<__nv_bfloat162*>(Bp + (size_t)n * 1536 + 1024 + kg);
    p0[0] = __nv_bfloat162(h[0], h[1]); p0[1] = __nv_bfloat162(h[2], h[3]);
    p1[0] = __nv_bfloat162(l[0], l[1]); p1[1] = __nv_bfloat162(l[2], l[3]);
    p2[0] = __nv_bfloat162(h[0], h[1]); p2[1] = __nv_bfloat162(h[2], h[3]);
}

// ============ HMMA bf16 GEMM ============
#define HG_A_BYTES 16384
#define HG_B_BYTES 16384
#define HG_SMEM_TOTAL (2 * (HG_A_BYTES + HG_B_BYTES))

__global__ __launch_bounds__(256, 2)
void mma_gemm_hmma(const __nv_bfloat16* __restrict__ Ap, const __nv_bfloat16* __restrict__ Bp,
                   float* __restrict__ C) {
    extern __shared__ char smemc[];
    uint32_t sb_a = smem_to_u32(smemc);
    uint32_t sb_b = sb_a + 2 * HG_A_BYTES;
    const int tid = threadIdx.x, lane = tid & 31, wid = tid >> 5;
    const int mt = blockIdx.y, nt = blockIdx.x;
    const int m0 = (wid & 3) * 32;
    const int n0 = (wid >> 2) * 64;

    const __nv_bfloat16* Ag = Ap + (size_t)mt * 128 * 1536;
    const __nv_bfloat16* Bg = Bp + (size_t)nt * 128 * 1536;

#define HLOAD(s, buf) { \
    uint32_t ab_ = sb_a + (buf) * HG_A_BYTES; \
    uint32_t bb_ = sb_b + (buf) * HG_B_BYTES; \
    const __nv_bfloat16* As_ = Ag + (s) * 64; \
    const __nv_bfloat16* Bs_ = Bg + (s) * 64; \
    _Pragma("unroll") \
    for (int i_ = 0; i_ < 4; i_++) { int ix_ = tid + i_ * 256; int r_ = ix_ >> 3, c_ = ix_ & 7; \
        cp_async16(ab_ + SW128(r_ * 128 + c_ * 16), As_ + (size_t)r_ * 1536 + c_ * 8); } \
    _Pragma("unroll") \
    for (int i_ = 0; i_ < 4; i_++) { int ix_ = tid + i_ * 256; int r_ = ix_ >> 3, c_ = ix_ & 7; \
        cp_async16(bb_ + SW128(r_ * 128 + c_ * 16), Bs_ + (size_t)r_ * 1536 + c_ * 8); } \
    CP_COMMIT(); }

    float acc[2][8][4];
#pragma unroll
    for (int i = 0; i < 2; i++)
#pragma unroll
        for (int j = 0; j < 8; j++)
#pragma unroll
            for (int v = 0; v < 4; v++) acc[i][j][v] = 0.f;

    HLOAD(0, 0);
    HLOAD(1, 1);

    const int a_row_off = ((lane >> 3) & 1) * 8 + (lane & 7);
    const int a_kb_off  = ((lane >> 4) & 1) * 16;
    const int b_row_off = ((lane >> 4) & 1) * 8 + (lane & 7);
    const int b_kb_off  = ((lane >> 3) & 1) * 16;

    for (int s = 0; s < 24; s++) {
        int buf = s & 1;
        CP_WAIT(1);
        __syncthreads();
        uint32_t abase = sb_a + buf * HG_A_BYTES;
        uint32_t bbase = sb_b + buf * HG_B_BYTES;
#pragma unroll
        for (int kk = 0; kk < 4; kk++) {
            uint32_t a[2][4];
#pragma unroll
            for (int mi = 0; mi < 2; mi++) {
                int row = m0 + mi * 16 + a_row_off;
                int kb = kk * 32 + a_kb_off;
                ldsm_x4(a[mi][0], a[mi][1], a[mi][2], a[mi][3], abase + SW128(row * 128 + kb));
            }
            uint32_t bfr[4][4];
#pragma unroll
            for (int ng = 0; ng < 4; ng++) {
                int row = n0 + ng * 16 + b_row_off;
                int kb = kk * 32 + b_kb_off;
                ldsm_x4(bfr[ng][0], bfr[ng][1], bfr[ng][2], bfr[ng][3], bbase + SW128(row * 128 + kb));
            }
#pragma unroll
            for (int mi = 0; mi < 2; mi++)
#pragma unroll
                for (int nj = 0; nj < 8; nj++) {
                    uint32_t b0 = bfr[nj >> 1][(nj & 1) * 2];
                    uint32_t b1 = bfr[nj >> 1][(nj & 1) * 2 + 1];
                    mma16816(acc[mi][nj][0], acc[mi][nj][1], acc[mi][nj][2], acc[mi][nj][3],
                             a[mi][0], a[mi][1], a[mi][2], a[mi][3], b0, b1);
                }
        }
        __syncthreads();
        if (s + 2 < 24) HLOAD(s + 2, buf);
    }

    int gr = mt * 128 + m0 + (lane >> 2);
    int gc = nt * 128 + n0 + (lane & 3) * 2;
#pragma unroll
    for (int mi = 0; mi < 2; mi++) {
#pragma unroll
        for (int nj = 0; nj < 8; nj++) {
            float* p0 = C + (size_t)(gr + mi * 16) * V_ + gc + nj * 8;
            float* p1 = C + (size_t)(gr + mi * 16 + 8) * V_ + gc + nj * 8;
            *reinterpret_cast<float2*>(p0) = make_float2(acc[mi][nj][0], acc[mi][nj][1]);
            *reinterpret_cast<float2*>(p1) = make_float2(acc[mi][nj][2], acc[mi][nj][3]);
        }
    }
}

// ---------------- host orchestration ----------------
extern "C" void kernel_launch(void* const* d_in, const int* in_sizes, int n_in,
                              void* d_out, int out_size) {
    const int*   tokens  = (const int*)d_in[0];
    const unsigned char* enc_mask = (const unsigned char*)d_in[1];
    const float* enc_out = (const float*)d_in[2];
    const float* embed_w = (const float*)d_in[3];
    const float* g1Wx = (const float*)d_in[4];
    const float* g1Wh = (const float*)d_in[5];
    const float* g1bx = (const float*)d_in[6];
    const float* g1bh = (const float*)d_in[7];
    const float* g2Wx = (const float*)d_in[8];
    const float* g2Wh = (const float*)d_in[9];
    const float* g2bx = (const float*)d_in[10];
    const float* g2bh = (const float*)d_in[11];
    const float* brW  = (const float*)d_in[12];
    const float* brB  = (const float*)d_in[13];
    const float* Wk   = (const float*)d_in[14];
    const float* bk   = (const float*)d_in[15];
    const float* Wq   = (const float*)d_in[16];
    const float* bq   = (const float*)d_in[17];
    const float* Ww   = (const float*)d_in[18];
    const float* bw   = (const float*)d_in[19];
    const float* Wf   = (const float*)d_in[20];
    const float* bf   = (const float*)d_in[21];
    const float* Wo   = (const float*)d_in[22];
    const float* bo   = (const float*)d_in[23];
    float* out = (float*)d_out;

    float* S = nullptr;
    cudaGetSymbolAddress((void**)&S, g_scratch);
    float* feat    = S + OFF_FEAT;
    float* keyup   = S + OFF_KEYUP;
    float* hT4     = S + OFF_HT;
    float* t4      = S + OFF_TMP;
    float* c4      = S + OFF_CTXRT;
    float* X1T     = S + OFF_X1ALL;
    float* Wfx2    = S + OFF_WFX2;
    float* bfx2    = S + OFF_BFX2;
    float* WqT     = S + OFF_WQT;
    float* WfT     = S + OFF_WFT;
    float* Wo2f    = S + OFF_WO2F;
    float* Wopk    = S + OFF_WOPK;
    float* bo2     = S + OFF_BO2;
    __nv_bfloat16* Ahl = (__nv_bfloat16*)(S + OFF_AHL);
    __nv_bfloat16* Bhl = (__nv_bfloat16*)(S + OFF_BHL);

    // ---- prep ----
    k_embed<<<B_ * T_, 128>>>(tokens, embed_w, feat);
    k_bridge<<<B_, 512>>>(enc_mask, enc_out, brW, brB, hT4);
    k_transpose<<<(512 * 512 + 255) / 256, 256>>>(Wq, WqT, 512, 512);
    k_transpose<<<(1024 * 1024 + 255) / 256, 256>>>(Wf, WfT, 1024, 1024);
    k_bfx2<<<6, 256>>>(g2Wx, bf, g2bx, bfx2);
    k_bo2<<<2, 256>>>(Wo, bf, bo, bo2);
    k_convB<<<(32000 * 128 + 255) / 256, 256>>>(embed_w, Bhl);
    {   // keyup = enc @ Wk^T + bk
        dim3 g(512 / BN, 2048 / BM);
        sgemm_nt<<<g, 256>>>(enc_out, Wk, bk, keyup, 2048, 512, 1024, 1024, 2);
    }
    {   // X1T = emb @ g1Wx^T + g1bx, stored [t][j][b]
        dim3 g(1536 / BN, 2048 / BM);
        sgemm_nt<<<g, 256>>>(feat, g1Wx, g1bx, X1T, 2048, 1536, 512, 2048, 3);
    }
    {   // Wfx2 = g2Wx (x) Wf
        dim3 g(1024 / BN, 1536 / BM);
        sgemm_nt<<<g, 256>>>(g2Wx, WfT, nullptr, Wfx2, 1536, 1024, 1024, 1024, 0);
    }
    {   // Wo2f[e][n] = sum_m Wo[e][1024+m] Wf[m][n]
        dim3 g(1024 / BN, 512 / BM);
        sgemm_nt<<<g, 256>>>(Wo + 1024, WfT, nullptr, Wo2f, 512, 1024, 1024, 2048, 0);
    }
    k_wopack<<<(512 * 2048 + 255) / 256, 256>>>(Wo, Wo2f, Wopk);

    // ---- persistent recurrence ----
    k_zero<<<1, 1>>>();
    cudaFuncSetAttribute(k_persistent, cudaFuncAttributeMaxDynamicSharedMemorySize, PERS_SMEM);
    k_persistent<<<NB, 512, PERS_SMEM>>>(X1T, g1Wh, g1bh, Wfx2, bfx2, g2Wh, g2bh,
                                         WqT, bq, Ww, bw,
                                         enc_out, enc_mask, keyup,
                                         feat, hT4, t4, c4);

    {   // logits = tanh(feat_pack @ Wopk^T + bo2) -> Ahl hi/lo directly (mode 4)
        dim3 g(512 / BN, 2048 / BM);
        sgemm_nt<<<g, 256>>>(feat, Wopk, bo2, (float*)Ahl, 2048, 512, 2048, 2048, 4);
    }
    cudaFuncSetAttribute(mma_gemm_hmma, cudaFuncAttributeMaxDynamicSharedMemorySize, HG_SMEM_TOTAL);
    {
        dim3 g(V_ / 128, 2048 / 128);
        mma_gemm_hmma<<<g, 256, HG_SMEM_TOTAL>>>(Ahl, Bhl, out);
    }
}

// round 15
// speedup vs baseline: 1.2057x; 1.0238x over previous
#include <cuda_runtime.h>
#include <cuda_bf16.h>
#include <math.h>
#include <stdint.h>

#define B_ 32
#define T_ 64
#define S_ 64
#define V_ 32000
#define E_ 512
#define H_ 512
#define U_ 1024
#define NH_ 8
#define FEATW 2048
#define NB 128
#define NBH 64    // blocks per independent half

// ---------------- scratch offsets (floats) ----------------
#define OFF_FEAT   0ull
#define OFF_KEYUP  4194304ull
#define OFF_LOGITS 5242880ull
#define OFF_HT     6291456ull     // hT4 [128 kg][32 b][4]
#define OFF_TMP    6307840ull     // t4 same layout
#define OFF_CTXRT  6340608ull     // c4 [256 kg][32 b][4]
#define OFF_X1ALL  6373376ull     // X1T [64 t][1536 j][32 b]
#define OFF_WFX2   9519104ull
#define OFF_BFX2   11091968ull
#define OFF_WQT    11094016ull
#define OFF_WFT    11356160ull
#define OFF_WO2F   12404736ull
#define OFF_WOPK   12929024ull
#define OFF_BO2    13977600ull
#define OFF_AHL    13978624ull    // [2048,1536] bf16
#define OFF_BHL    15551488ull    // [32000,1536] bf16
#define SCRATCH_FLOATS 40127488ull

__device__ float g_scratch[SCRATCH_FLOATS];
__device__ unsigned g_bar2[64];   // counter 0 at [0], counter 1 at [32] (128B apart)

__device__ __forceinline__ uint32_t smem_to_u32(const void* p) {
    uint32_t a;
    asm("{ .reg .u64 t; cvta.to.shared.u64 t, %1; cvt.u32.u64 %0, t; }" : "=r"(a) : "l"(p));
    return a;
}
__device__ __forceinline__ void cp_async16(uint32_t dst, const void* src) {
    asm volatile("cp.async.cg.shared.global [%0], [%1], 16;" :: "r"(dst), "l"(src));
}
#define CP_COMMIT() asm volatile("cp.async.commit_group;" ::: "memory")
#define CP_WAIT(n)  asm volatile("cp.async.wait_group %0;" :: "n"(n) : "memory")
#define SW128(x) ((x) ^ (((x) >> 3) & 0x70))

__device__ __forceinline__ void ldsm_x4(uint32_t& r0, uint32_t& r1, uint32_t& r2, uint32_t& r3,
                                        uint32_t addr) {
    asm volatile("ldmatrix.sync.aligned.m8n8.x4.shared.b16 {%0,%1,%2,%3}, [%4];"
                 : "=r"(r0), "=r"(r1), "=r"(r2), "=r"(r3) : "r"(addr));
}
__device__ __forceinline__ void mma16816(float& c0, float& c1, float& c2, float& c3,
                                         uint32_t a0, uint32_t a1, uint32_t a2, uint32_t a3,
                                         uint32_t b0, uint32_t b1) {
    asm volatile("mma.sync.aligned.m16n8k16.row.col.f32.bf16.bf16.f32 "
                 "{%0,%1,%2,%3}, {%4,%5,%6,%7}, {%8,%9}, {%0,%1,%2,%3};"
                 : "+f"(c0), "+f"(c1), "+f"(c2), "+f"(c3)
                 : "r"(a0), "r"(a1), "r"(a2), "r"(a3), "r"(b0), "r"(b1));
}

// FROZEN barrier form (R9/R11), now per-half: 64 arrivals on this half's counter.
__device__ __forceinline__ void gsync(unsigned& gen, unsigned* ctr) {
    __syncthreads();
    if (threadIdx.x == 0) {
        __threadfence();
        atomicAdd(ctr, 1u);
        unsigned target = (gen + 1u) * (unsigned)NBH;
        unsigned v;
        do {
            asm volatile("ld.acquire.gpu.u32 %0, [%1];" : "=r"(v) : "l"(ctr) : "memory");
            if (v < target) __nanosleep(32);
        } while (v < target);
    }
    gen++;
    __syncthreads();
}
__global__ void k_zero() { g_bar2[0] = 0u; g_bar2[32] = 0u; }

// ---------------- prep kernels ----------------
__global__ void k_embed(const int* __restrict__ tokens, const float* __restrict__ embed_w,
                        float* __restrict__ feat) {
    int bt = blockIdx.x;
    int tok = tokens[bt];
    const float4* src = reinterpret_cast<const float4*>(embed_w + (size_t)tok * E_);
    float4* dst = reinterpret_cast<float4*>(feat + (size_t)bt * FEATW);
    dst[threadIdx.x] = src[threadIdx.x];
}

__global__ __launch_bounds__(512) void k_bridge(const unsigned char* __restrict__ mask,
                                                const float* __restrict__ enc_out,
                                                const float* __restrict__ Wb,
                                                const float* __restrict__ bb,
                                                float* __restrict__ hT4) {
    int b = blockIdx.x;
    int j = threadIdx.x;
    __shared__ float fn[512];
    __shared__ int sL;
    if (j == 0) {
        int L = S_;
        for (int s = 0; s < S_; s++) if (mask[b * S_ + s]) L--;
        sL = L;
    }
    __syncthreads();
    int L = sL;
    fn[j] = enc_out[((size_t)(L - 1) * B_ + b) * U_ + j];
    __syncthreads();
    float acc = bb[j];
    const float* wr = Wb + (size_t)j * 512;
    for (int k = 0; k < 512; k++) acc += fn[k] * wr[k];
    hT4[(j >> 2) * 128 + b * 4 + (j & 3)] = tanhf(acc);
}

__global__ void k_transpose(const float* __restrict__ W, float* __restrict__ WT, int R, int C) {
    int idx = blockIdx.x * 256 + threadIdx.x;
    if (idx >= R * C) return;
    int n = idx / C, k = idx % C;
    WT[(size_t)k * R + n] = W[idx];
}

__global__ void k_bfx2(const float* __restrict__ g2Wx, const float* __restrict__ bf,
                       const float* __restrict__ g2bx, float* __restrict__ bfx2) {
    int g = blockIdx.x * 256 + threadIdx.x;
    if (g >= 1536) return;
    float a = g2bx[g];
    const float4* w4 = reinterpret_cast<const float4*>(g2Wx + (size_t)g * 1024);
    const float4* b4 = reinterpret_cast<const float4*>(bf);
    for (int k = 0; k < 256; k++) {
        float4 w = w4[k], b = b4[k];
        a += w.x * b.x + w.y * b.y + w.z * b.z + w.w * b.w;
    }
    bfx2[g] = a;
}

__global__ void k_wopack(const float* __restrict__ Wo, const float* __restrict__ Wo2f,
                         float* __restrict__ Wp) {
    int idx = blockIdx.x * 256 + threadIdx.x;
    if (idx >= 512 * 2048) return;
    int e = idx >> 11, c = idx & 2047;
    Wp[idx] = (c < 1024) ? Wo[(size_t)e * 2048 + c] : Wo2f[(size_t)e * 1024 + (c - 1024)];
}
__global__ void k_bo2(const float* __restrict__ Wo, const float* __restrict__ bf,
                      const float* __restrict__ bo, float* __restrict__ bo2) {
    int e = blockIdx.x * 256 + threadIdx.x;
    if (e >= 512) return;
    float a = bo[e];
    const float* w = Wo + (size_t)e * 2048 + 1024;
    for (int m = 0; m < 1024; m++) a += w[m] * bf[m];
    bo2[e] = a;
}

// ---------------- tiled SGEMM-NT with lda ----------------
// mode 0 plain, 1 tanh, 2 keyup remap, 3 X1T remap, 4 tanh + bf16 hi/lo split into Ahl
#define BM 128
#define BN 128
#define BKk 16
__global__ __launch_bounds__(256) void sgemm_nt(const float* __restrict__ A,
                                                const float* __restrict__ Bm,
                                                const float* __restrict__ bias,
                                                float* __restrict__ C,
                                                int M, int N, int K, int lda, int mode) {
    __shared__ float As[BKk][BM];
    __shared__ float Bs[BKk][BN];
    const int bm = blockIdx.y * BM, bn = blockIdx.x * BN;
    const int tid = threadIdx.x;
    const int tm = (tid >> 4) << 3;
    const int tn = (tid & 15) << 3;
    float acc[8][8];
#pragma unroll
    for (int i = 0; i < 8; i++)
#pragma unroll
        for (int j = 0; j < 8; j++) acc[i][j] = 0.f;

    for (int k0 = 0; k0 < K; k0 += BKk) {
#pragma unroll
        for (int i = 0; i < 2; i++) {
            int idx = tid + i * 256;
            int r = idx >> 2, c = (idx & 3) << 2;
            float4 v = *reinterpret_cast<const float4*>(A + (size_t)(bm + r) * lda + k0 + c);
            As[c][r] = v.x; As[c + 1][r] = v.y; As[c + 2][r] = v.z; As[c + 3][r] = v.w;
            float4 w = *reinterpret_cast<const float4*>(Bm + (size_t)(bn + r) * K + k0 + c);
            Bs[c][r] = w.x; Bs[c + 1][r] = w.y; Bs[c + 2][r] = w.z; Bs[c + 3][r] = w.w;
        }
        __syncthreads();
#pragma unroll
        for (int k = 0; k < BKk; k++) {
            float a[8], bb[8];
            *reinterpret_cast<float4*>(&a[0]) = *reinterpret_cast<const float4*>(&As[k][tm]);
            *reinterpret_cast<float4*>(&a[4]) = *reinterpret_cast<const float4*>(&As[k][tm + 4]);
            *reinterpret_cast<float4*>(&bb[0]) = *reinterpret_cast<const float4*>(&Bs[k][tn]);
            *reinterpret_cast<float4*>(&bb[4]) = *reinterpret_cast<const float4*>(&Bs[k][tn + 4]);
#pragma unroll
            for (int i = 0; i < 8; i++)
#pragma unroll
                for (int j = 0; j < 8; j++) acc[i][j] += a[i] * bb[j];
        }
        __syncthreads();
    }
#pragma unroll
    for (int i = 0; i < 8; i++) {
        int m = bm + tm + i;
#pragma unroll
        for (int j = 0; j < 8; j++) {
            int n = bn + tn + j;
            float v = acc[i][j];
            if (bias) v += bias[n];
            if (mode == 1) v = tanhf(v);
            if (mode == 2) {
                int s_ = m >> 5, b_ = m & 31, nh_ = n >> 6, d_ = n & 63;
                C[(((size_t)(b_ * 8 + nh_) * 64) + s_) * 64 + d_] = v;
            } else if (mode == 3) {
                int b_ = m >> 6, t_ = m & 63;
                C[((size_t)t_ * 1536 + n) * 32 + b_] = v;
            } else if (mode == 4) {
                v = tanhf(v);
                __nv_bfloat16* Ahl = reinterpret_cast<__nv_bfloat16*>(C);
                __nv_bfloat16 hi = __float2bfloat16(v);
                __nv_bfloat16 lo = __float2bfloat16(v - __bfloat162float(hi));
                Ahl[(size_t)m * 1536 + n] = hi;
                Ahl[(size_t)m * 1536 + 512 + n] = hi;
                Ahl[(size_t)m * 1536 + 1024 + n] = lo;
            } else {
                C[(size_t)m * N + n] = v;
            }
        }
    }
}

// ---------------- persistent recurrence (two independent 64-block halves) ----------------
#define PERS_SMEM (51200 * 4)

__global__ __launch_bounds__(512, 1)
void k_persistent(const float* __restrict__ X1T, const float* __restrict__ g1Wh,
                  const float* __restrict__ g1bh,
                  const float* __restrict__ Wfx2, const float* __restrict__ bfx2,
                  const float* __restrict__ g2Wh, const float* __restrict__ g2bh,
                  const float* __restrict__ WqT, const float* __restrict__ bq,
                  const float* __restrict__ Ww, const float* __restrict__ bw,
                  const float* __restrict__ enc_out, const unsigned char* __restrict__ mask,
                  const float* __restrict__ keyup,
                  float* __restrict__ feat, float* __restrict__ hT4,
                  float* __restrict__ t4, float* __restrict__ c4) {
    extern __shared__ float sm[];
    float* W1s  = sm;
    float* W2xs = sm + 12288;
    float* W2hs = sm + 36864;
    float* scr  = sm + 49152;
    const int bid = blockIdx.x, tid = threadIdx.x;
    unsigned gen = 0;
    const int bl = tid & 15, jl = (tid >> 4) & 7, q = tid >> 7;
    const int jb = bid >> 1, bh = bid & 1;
    const int j0 = jb * 8, b0 = bh * 16;
    unsigned* ctr = &g_bar2[bh * 32];     // per-half barrier counter (128B apart)

    // stage loop-invariant weights ONCE
    {
        float4* d1 = reinterpret_cast<float4*>(W1s);
        for (int i = tid; i < 3072; i += 512) {
            int jj = i / 384, rem = i % 384, g = rem >> 7, k4 = rem & 127;
            d1[i] = *reinterpret_cast<const float4*>(
                g1Wh + ((size_t)(g * 512 + j0 + jj)) * 512 + k4 * 4);
        }
        float4* d2 = reinterpret_cast<float4*>(W2xs);
        for (int i = tid; i < 6144; i += 512) {
            int jj = i / 768, rem = i % 768, g = rem >> 8, k4 = rem & 255;
            d2[i] = *reinterpret_cast<const float4*>(
                Wfx2 + ((size_t)(g * 512 + j0 + jj)) * 1024 + k4 * 4);
        }
        float4* d3 = reinterpret_cast<float4*>(W2hs);
        for (int i = tid; i < 3072; i += 512) {
            int jj = i / 384, rem = i % 384, g = rem >> 7, k4 = rem & 127;
            d3[i] = *reinterpret_cast<const float4*>(
                g2Wh + ((size_t)(g * 512 + j0 + jj)) * 512 + k4 * 4);
        }
    }
    __syncthreads();

    float h_r, h_z, h_hn;

    for (int t = 0; t < T_; t++) {
        // ============ P1: GRU1 h-gates + combine ============
        float ar = 0.f, az = 0.f, an = 0.f;
        {
            const float4* xp = reinterpret_cast<const float4*>(hT4) + q * 1024 + b0 + bl;
            const float4* wr4 = reinterpret_cast<const float4*>(W1s + (jl * 3 + 0) * 512) + q * 32;
            const float4* wz4 = reinterpret_cast<const float4*>(W1s + (jl * 3 + 1) * 512) + q * 32;
            const float4* wn4 = reinterpret_cast<const float4*>(W1s + (jl * 3 + 2) * 512) + q * 32;
#pragma unroll 8
            for (int kk = 0; kk < 32; kk++) {
                float4 x = __ldcg(xp + kk * 32);
                float4 wr = wr4[kk], wz = wz4[kk], wn = wn4[kk];
                ar += x.x * wr.x + x.y * wr.y + x.z * wr.z + x.w * wr.w;
                az += x.x * wz.x + x.y * wz.y + x.z * wz.z + x.w * wz.w;
                an += x.x * wn.x + x.y * wn.y + x.z * wn.z + x.w * wn.w;
            }
            if (q) {
                int o = (q - 1) * 384 + (jl * 16 + bl) * 3;
                scr[o] = ar; scr[o + 1] = az; scr[o + 2] = an;
            }
        }
        __syncthreads();
        if (q == 0) {
            int o = (jl * 16 + bl) * 3;
            ar += scr[o] + scr[384 + o] + scr[768 + o];
            az += scr[o + 1] + scr[384 + o + 1] + scr[768 + o + 1];
            an += scr[o + 2] + scr[384 + o + 2] + scr[768 + o + 2];
            int j = j0 + jl, b = b0 + bl;
            const float* X1 = X1T + ((size_t)t * 1536) * 32;
            float xr = X1[(size_t)j * 32 + b];
            float xz = X1[(size_t)(512 + j) * 32 + b];
            float xn = X1[(size_t)(1024 + j) * 32 + b];
            float r = 1.f / (1.f + expf(-(xr + g1bh[j] + ar)));
            float z = 1.f / (1.f + expf(-(xz + g1bh[512 + j] + az)));
            float n = tanhf(xn + r * (an + g1bh[1024 + j]));
            float hp = __ldcg(hT4 + (j >> 2) * 128 + b * 4 + (j & 3));
            float o2 = (1.f - z) * n + z * hp;
            t4[(j >> 2) * 128 + b * 4 + (j & 3)] = o2;
        }
        gsync(gen, ctr);

        // ============ P2: attention (half-local pairs) + GRU2 h-part ============
        {
            int pr = tid >> 8, tid2 = tid & 255;
            int p_local = (bid & ~1) + pr;            // 0..127 within this half
            int b = b0 + (p_local >> 3), nh = p_local & 7;
            float* st  = scr + pr * 512;
            float* sq  = scr + 1024 + pr * 64;
            float* sa  = scr + 1152 + pr * 64;
            float* qp  = scr + 1280 + pr * 256;
            float* scp = scr + 1792 + pr * 128;
            for (int i = tid2; i < 512; i += 256)
                st[i] = __ldcg(t4 + (i >> 2) * 128 + b * 4 + (i & 3));
            __syncthreads();
            {
                int d = tid2 & 63, kq = tid2 >> 6;
                float a = 0.f;
                const float* wp = WqT + nh * 64 + d;
                int k0 = kq * 128;
#pragma unroll 16
                for (int k = k0; k < k0 + 128; k++) a += st[k] * wp[(size_t)k * 512];
                qp[kq * 64 + d] = a;
            }
            __syncthreads();
            if (tid2 < 64)
                sq[tid2] = bq[nh * 64 + tid2] + qp[tid2] + qp[64 + tid2] + qp[128 + tid2] + qp[192 + tid2];
            __syncthreads();
            if (tid2 < 128) {
                int s = tid2 & 63, dh = tid2 >> 6;
                float a = 0.f;
                const float* kp = keyup + (((size_t)(b * 8 + nh)) * 64 + s) * 64 + dh * 32;
                const float* sqh = sq + dh * 32;
                const float* wwh = Ww + dh * 32;
#pragma unroll 8
                for (int d = 0; d < 32; d++) a += tanhf(sqh[d] + kp[d]) * wwh[d];
                scp[dh * 64 + s] = a;
            }
            __syncthreads();
            if (tid2 < 64) {
                float sc = scp[tid2] + scp[64 + tid2] + bw[0];
                if (mask[b * S_ + tid2]) sc -= 1e9f;
                sa[tid2] = sc;
            }
            __syncthreads();
            if (tid2 < 32) {
                float v0 = sa[tid2], v1 = sa[tid2 + 32];
                float mx = fmaxf(v0, v1);
#pragma unroll
                for (int o = 16; o; o >>= 1) mx = fmaxf(mx, __shfl_xor_sync(0xffffffffu, mx, o));
                float e0 = expf(v0 - mx), e1 = expf(v1 - mx);
                float sum = e0 + e1;
#pragma unroll
                for (int o = 16; o; o >>= 1) sum += __shfl_xor_sync(0xffffffffu, sum, o);
                float inv = 1.f / sum;
                sa[tid2] = e0 * inv;
                sa[tid2 + 32] = e1 * inv;
            }
            __syncthreads();
            if (tid2 < 128) {
                float a = 0.f;
                const float* vp = enc_out + (size_t)b * U_ + nh * 128 + tid2;
#pragma unroll
                for (int s = 0; s < 64; s++) a += sa[s] * vp[(size_t)s * B_ * U_];
                int n = nh * 128 + tid2;
                c4[(n >> 2) * 128 + b * 4 + (n & 3)] = a;
                feat[((size_t)b * T_ + t) * FEATW + 1024 + n] = a;
            }
        }
        // GRU2 h-part overlap
        {
            h_r = 0.f; h_z = 0.f; h_hn = 0.f;
            const float4* xp = reinterpret_cast<const float4*>(t4) + q * 1024 + b0 + bl;
            const float4* wr4 = reinterpret_cast<const float4*>(W2hs + (jl * 3 + 0) * 512) + q * 32;
            const float4* wz4 = reinterpret_cast<const float4*>(W2hs + (jl * 3 + 1) * 512) + q * 32;
            const float4* wn4 = reinterpret_cast<const float4*>(W2hs + (jl * 3 + 2) * 512) + q * 32;
#pragma unroll 8
            for (int kk = 0; kk < 32; kk++) {
                float4 x = __ldcg(xp + kk * 32);
                float4 wr = wr4[kk], wz = wz4[kk], wn = wn4[kk];
                h_r  += x.x * wr.x + x.y * wr.y + x.z * wr.z + x.w * wr.w;
                h_z  += x.x * wz.x + x.y * wz.y + x.z * wz.z + x.w * wz.w;
                h_hn += x.x * wn.x + x.y * wn.y + x.z * wn.z + x.w * wn.w;
            }
        }
        gsync(gen, ctr);

        // ============ P3: GRU2 x-part + combine ============
        float a_r = h_r, a_z = h_z, a_xn = 0.f, a_hn = h_hn;
        {
            const float4* xp = reinterpret_cast<const float4*>(c4) + q * 2048 + b0 + bl;
            const float4* wr4 = reinterpret_cast<const float4*>(W2xs + (jl * 3 + 0) * 1024) + q * 64;
            const float4* wz4 = reinterpret_cast<const float4*>(W2xs + (jl * 3 + 1) * 1024) + q * 64;
            const float4* wn4 = reinterpret_cast<const float4*>(W2xs + (jl * 3 + 2) * 1024) + q * 64;
#pragma unroll 8
            for (int kk = 0; kk < 64; kk++) {
                float4 x = __ldcg(xp + kk * 32);
                float4 wr = wr4[kk], wz = wz4[kk], wn = wn4[kk];
                a_r  += x.x * wr.x + x.y * wr.y + x.z * wr.z + x.w * wr.w;
                a_z  += x.x * wz.x + x.y * wz.y + x.z * wz.z + x.w * wz.w;
                a_xn += x.x * wn.x + x.y * wn.y + x.z * wn.z + x.w * wn.w;
            }
            if (q) {
                int o = (q - 1) * 512 + (jl * 16 + bl) * 4;
                scr[o] = a_r; scr[o + 1] = a_z; scr[o + 2] = a_xn; scr[o + 3] = a_hn;
            }
        }
        __syncthreads();
        if (q == 0) {
            int o = (jl * 16 + bl) * 4;
            a_r  += scr[o] + scr[512 + o] + scr[1024 + o];
            a_z  += scr[o + 1] + scr[512 + o + 1] + scr[1024 + o + 1];
            a_xn += scr[o + 2] + scr[512 + o + 2] + scr[1024 + o + 2];
            a_hn += scr[o + 3] + scr[512 + o + 3] + scr[1024 + o + 3];
            int j = j0 + jl, b = b0 + bl, m = b * T_ + t;
            float r = 1.f / (1.f + expf(-(a_r + bfx2[j] + g2bh[j])));
            float z = 1.f / (1.f + expf(-(a_z + bfx2[512 + j] + g2bh[512 + j])));
            float n = tanhf(a_xn + bfx2[1024 + j] + r * (a_hn + g2bh[1024 + j]));
            float hp = __ldcg(t4 + (j >> 2) * 128 + b * 4 + (j & 3));
            float o2 = (1.f - z) * n + z * hp;
            hT4[(j >> 2) * 128 + b * 4 + (j & 3)] = o2;
            feat[(size_t)m * FEATW + 512 + j] = o2;
        }
        gsync(gen, ctr);
    }
}

// ============ bf16 hi/lo split for embed_w ============
__global__ void k_convB(const float* __restrict__ W, __nv_bfloat16* __restrict__ Bp) {
    int idx = blockIdx.x * 256 + threadIdx.x;
    if (idx >= 32000 * 128) return;
    int n = idx >> 7, kg = (idx & 127) << 2;
    float4 v = *reinterpret_cast<const float4*>(W + (size_t)n * 512 + kg);
    __nv_bfloat16 h[4], l[4];
    float x[4] = {v.x, v.y, v.z, v.w};
#pragma unroll
    for (int i = 0; i < 4; i++) {
        h[i] = __float2bfloat16(x[i]);
        l[i] = __float2bfloat16(x[i] - __bfloat162float(h[i]));
    }
    __nv_bfloat162* p0 = reinterpret_cast<__nv_bfloat162*>(Bp + (size_t)n * 1536 + kg);
    __nv_bfloat162* p1 = reinterpret_cast<__nv_bfloat162*>(Bp + (size_t)n * 1536 + 512 + kg);
    __nv_bfloat162* p2 = reinterpret_cast<__nv_bfloat162*>(Bp + (size_t)n * 1536 + 1024 + kg);
    p0[0] = __nv_bfloat162(h[0], h[1]); p0[1] = __nv_bfloat162(h[2], h[3]);
    p1[0] = __nv_bfloat162(l[0], l[1]); p1[1] = __nv_bfloat162(l[2], l[3]);
    p2[0] = __nv_bfloat162(h[0], h[1]); p2[1] = __nv_bfloat162(h[2], h[3]);
}

// ============ HMMA bf16 GEMM ============
#define HG_A_BYTES 16384
#define HG_B_BYTES 16384
#define HG_SMEM_TOTAL (2 * (HG_A_BYTES + HG_B_BYTES))

__global__ __launch_bounds__(256, 2)
void mma_gemm_hmma(const __nv_bfloat16* __restrict__ Ap, const __nv_bfloat16* __restrict__ Bp,
                   float* __restrict__ C) {
    extern __shared__ char smemc[];
    uint32_t sb_a = smem_to_u32(smemc);
    uint32_t sb_b = sb_a + 2 * HG_A_BYTES;
    const int tid = threadIdx.x, lane = tid & 31, wid = tid >> 5;
    const int mt = blockIdx.y, nt = blockIdx.x;
    const int m0 = (wid & 3) * 32;
    const int n0 = (wid >> 2) * 64;

    const __nv_bfloat16* Ag = Ap + (size_t)mt * 128 * 1536;
    const __nv_bfloat16* Bg = Bp + (size_t)nt * 128 * 1536;

#define HLOAD(s, buf) { \
    uint32_t ab_ = sb_a + (buf) * HG_A_BYTES; \
    uint32_t bb_ = sb_b + (buf) * HG_B_BYTES; \
    const __nv_bfloat16* As_ = Ag + (s) * 64; \
    const __nv_bfloat16* Bs_ = Bg + (s) * 64; \
    _Pragma("unroll") \
    for (int i_ = 0; i_ < 4; i_++) { int ix_ = tid + i_ * 256; int r_ = ix_ >> 3, c_ = ix_ & 7; \
        cp_async16(ab_ + SW128(r_ * 128 + c_ * 16), As_ + (size_t)r_ * 1536 + c_ * 8); } \
    _Pragma("unroll") \
    for (int i_ = 0; i_ < 4; i_++) { int ix_ = tid + i_ * 256; int r_ = ix_ >> 3, c_ = ix_ & 7; \
        cp_async16(bb_ + SW128(r_ * 128 + c_ * 16), Bs_ + (size_t)r_ * 1536 + c_ * 8); } \
    CP_COMMIT(); }

    float acc[2][8][4];
#pragma unroll
    for (int i = 0; i < 2; i++)
#pragma unroll
        for (int j = 0; j < 8; j++)
#pragma unroll
            for (int v = 0; v < 4; v++) acc[i][j][v] = 0.f;

    HLOAD(0, 0);
    HLOAD(1, 1);

    const int a_row_off = ((lane >> 3) & 1) * 8 + (lane & 7);
    const int a_kb_off  = ((lane >> 4) & 1) * 16;
    const int b_row_off = ((lane >> 4) & 1) * 8 + (lane & 7);
    const int b_kb_off  = ((lane >> 3) & 1) * 16;

    for (int s = 0; s < 24; s++) {
        int buf = s & 1;
        CP_WAIT(1);
        __syncthreads();
        uint32_t abase = sb_a + buf * HG_A_BYTES;
        uint32_t bbase = sb_b + buf * HG_B_BYTES;
#pragma unroll
        for (int kk = 0; kk < 4; kk++) {
            uint32_t a[2][4];
#pragma unroll
            for (int mi = 0; mi < 2; mi++) {
                int row = m0 + mi * 16 + a_row_off;
                int kb = kk * 32 + a_kb_off;
                ldsm_x4(a[mi][0], a[mi][1], a[mi][2], a[mi][3], abase + SW128(row * 128 + kb));
            }
            uint32_t bfr[4][4];
#pragma unroll
            for (int ng = 0; ng < 4; ng++) {
                int row = n0 + ng * 16 + b_row_off;
                int kb = kk * 32 + b_kb_off;
                ldsm_x4(bfr[ng][0], bfr[ng][1], bfr[ng][2], bfr[ng][3], bbase + SW128(row * 128 + kb));
            }
#pragma unroll
            for (int mi = 0; mi < 2; mi++)
#pragma unroll
                for (int nj = 0; nj < 8; nj++) {
                    uint32_t b0 = bfr[nj >> 1][(nj & 1) * 2];
                    uint32_t b1 = bfr[nj >> 1][(nj & 1) * 2 + 1];
                    mma16816(acc[mi][nj][0], acc[mi][nj][1], acc[mi][nj][2], acc[mi][nj][3],
                             a[mi][0], a[mi][1], a[mi][2], a[mi][3], b0, b1);
                }
        }
        __syncthreads();
        if (s + 2 < 24) HLOAD(s + 2, buf);
    }

    int gr = mt * 128 + m0 + (lane >> 2);
    int gc = nt * 128 + n0 + (lane & 3) * 2;
#pragma unroll
    for (int mi = 0; mi < 2; mi++) {
#pragma unroll
        for (int nj = 0; nj < 8; nj++) {
            float* p0 = C + (size_t)(gr + mi * 16) * V_ + gc + nj * 8;
            float* p1 = C + (size_t)(gr + mi * 16 + 8) * V_ + gc + nj * 8;
            *reinterpret_cast<float2*>(p0) = make_float2(acc[mi][nj][0], acc[mi][nj][1]);
            *reinterpret_cast<float2*>(p1) = make_float2(acc[mi][nj][2], acc[mi][nj][3]);
        }
    }
}

// ---------------- host orchestration ----------------
extern "C" void kernel_launch(void* const* d_in, const int* in_sizes, int n_in,
                              void* d_out, int out_size) {
    const int*   tokens  = (const int*)d_in[0];
    const unsigned char* enc_mask = (const unsigned char*)d_in[1];
    const float* enc_out = (const float*)d_in[2];
    const float* embed_w = (const float*)d_in[3];
    const float* g1Wx = (const float*)d_in[4];
    const float* g1Wh = (const float*)d_in[5];
    const float* g1bx = (const float*)d_in[6];
    const float* g1bh = (const float*)d_in[7];
    const float* g2Wx = (const float*)d_in[8];
    const float* g2Wh = (const float*)d_in[9];
    const float* g2bx = (const float*)d_in[10];
    const float* g2bh = (const float*)d_in[11];
    const float* brW  = (const float*)d_in[12];
    const float* brB  = (const float*)d_in[13];
    const float* Wk   = (const float*)d_in[14];
    const float* bk   = (const float*)d_in[15];
    const float* Wq   = (const float*)d_in[16];
    const float* bq   = (const float*)d_in[17];
    const float* Ww   = (const float*)d_in[18];
    const float* bw   = (const float*)d_in[19];
    const float* Wf   = (const float*)d_in[20];
    const float* bf   = (const float*)d_in[21];
    const float* Wo   = (const float*)d_in[22];
    const float* bo   = (const float*)d_in[23];
    float* out = (float*)d_out;

    float* S = nullptr;
    cudaGetSymbolAddress((void**)&S, g_scratch);
    float* feat    = S + OFF_FEAT;
    float* keyup   = S + OFF_KEYUP;
    float* hT4     = S + OFF_HT;
    float* t4      = S + OFF_TMP;
    float* c4      = S + OFF_CTXRT;
    float* X1T     = S + OFF_X1ALL;
    float* Wfx2    = S + OFF_WFX2;
    float* bfx2    = S + OFF_BFX2;
    float* WqT     = S + OFF_WQT;
    float* WfT     = S + OFF_WFT;
    float* Wo2f    = S + OFF_WO2F;
    float* Wopk    = S + OFF_WOPK;
    float* bo2     = S + OFF_BO2;
    __nv_bfloat16* Ahl = (__nv_bfloat16*)(S + OFF_AHL);
    __nv_bfloat16* Bhl = (__nv_bfloat16*)(S + OFF_BHL);

    // ---- prep ----
    k_embed<<<B_ * T_, 128>>>(tokens, embed_w, feat);
    k_bridge<<<B_, 512>>>(enc_mask, enc_out, brW, brB, hT4);
    k_transpose<<<(512 * 512 + 255) / 256, 256>>>(Wq, WqT, 512, 512);
    k_transpose<<<(1024 * 1024 + 255) / 256, 256>>>(Wf, WfT, 1024, 1024);
    k_bfx2<<<6, 256>>>(g2Wx, bf, g2bx, bfx2);
    k_bo2<<<2, 256>>>(Wo, bf, bo, bo2);
    k_convB<<<(32000 * 128 + 255) / 256, 256>>>(embed_w, Bhl);
    {   // keyup = enc @ Wk^T + bk
        dim3 g(512 / BN, 2048 / BM);
        sgemm_nt<<<g, 256>>>(enc_out, Wk, bk, keyup, 2048, 512, 1024, 1024, 2);
    }
    {   // X1T = emb @ g1Wx^T + g1bx, stored [t][j][b]
        dim3 g(1536 / BN, 2048 / BM);
        sgemm_nt<<<g, 256>>>(feat, g1Wx, g1bx, X1T, 2048, 1536, 512, 2048, 3);
    }
    {   // Wfx2 = g2Wx (x) Wf
        dim3 g(1024 / BN, 1536 / BM);
        sgemm_nt<<<g, 256>>>(g2Wx, WfT, nullptr, Wfx2, 1536, 1024, 1024, 1024, 0);
    }
    {   // Wo2f[e][n] = sum_m Wo[e][1024+m] Wf[m][n]
        dim3 g(1024 / BN, 512 / BM);
        sgemm_nt<<<g, 256>>>(Wo + 1024, WfT, nullptr, Wo2f, 512, 1024, 1024, 2048, 0);
    }
    k_wopack<<<(512 * 2048 + 255) / 256, 256>>>(Wo, Wo2f, Wopk);

    // ---- persistent recurrence ----
    k_zero<<<1, 1>>>();
    cudaFuncSetAttribute(k_persistent, cudaFuncAttributeMaxDynamicSharedMemorySize, PERS_SMEM);
    k_persistent<<<NB, 512, PERS_SMEM>>>(X1T, g1Wh, g1bh, Wfx2, bfx2, g2Wh, g2bh,
                                         WqT, bq, Ww, bw,
                                         enc_out, enc_mask, keyup,
                                         feat, hT4, t4, c4);

    {   // logits = tanh(feat_pack @ Wopk^T + bo2) -> Ahl hi/lo directly (mode 4)
        dim3 g(512 / BN, 2048 / BM);
        sgemm_nt<<<g, 256>>>(feat, Wopk, bo2, (float*)Ahl, 2048, 512, 2048, 2048, 4);
    }
    cudaFuncSetAttribute(mma_gemm_hmma, cudaFuncAttributeMaxDynamicSharedMemorySize, HG_SMEM_TOTAL);
    {
        dim3 g(V_ / 128, 2048 / 128);
        mma_gemm_hmma<<<g, 256, HG_SMEM_TOTAL>>>(Ahl, Bhl, out);
    }
}

// round 16
// speedup vs baseline: 1.3370x; 1.1089x over previous
#include <cuda_runtime.h>
#include <cuda_bf16.h>
#include <math.h>
#include <stdint.h>

#define B_ 32
#define T_ 64
#define S_ 64
#define V_ 32000
#define E_ 512
#define H_ 512
#define U_ 1024
#define NH_ 8
#define FEATW 2048
#define NB 128
#define NBH 64

// ---------------- scratch offsets (floats) ----------------
#define OFF_FEAT   0ull
#define OFF_KEYUP  4194304ull
#define OFF_LOGITS 5242880ull
#define OFF_HT     6291456ull
#define OFF_TMP    6307840ull
#define OFF_CTXRT  6340608ull
#define OFF_X1ALL  6373376ull
#define OFF_WFX2   9519104ull
#define OFF_BFX2   11091968ull
#define OFF_WQT    11094016ull
#define OFF_WFT    11356160ull
#define OFF_WO2F   12404736ull
#define OFF_WOPK   12929024ull
#define OFF_BO2    13977600ull
#define OFF_AHL    13978624ull    // [2048,1536] bf16
#define OFF_BHL    15551488ull    // [32000,1536] bf16
#define OFF_FHL    40127488ull    // [2048,6144] bf16 = 6,291,456 floats
#define OFF_WOHL   46418944ull    // [512,6144] bf16 = 1,572,864 floats
#define SCRATCH_FLOATS 47991808ull

__device__ float g_scratch[SCRATCH_FLOATS];
__device__ unsigned g_bar2[64];

__device__ __forceinline__ uint32_t smem_to_u32(const void* p) {
    uint32_t a;
    asm("{ .reg .u64 t; cvta.to.shared.u64 t, %1; cvt.u32.u64 %0, t; }" : "=r"(a) : "l"(p));
    return a;
}
__device__ __forceinline__ void cp_async16(uint32_t dst, const void* src) {
    asm volatile("cp.async.cg.shared.global [%0], [%1], 16;" :: "r"(dst), "l"(src));
}
#define CP_COMMIT() asm volatile("cp.async.commit_group;" ::: "memory")
#define CP_WAIT(n)  asm volatile("cp.async.wait_group %0;" :: "n"(n) : "memory")
#define SW128(x) ((x) ^ (((x) >> 3) & 0x70))

__device__ __forceinline__ void ldsm_x4(uint32_t& r0, uint32_t& r1, uint32_t& r2, uint32_t& r3,
                                        uint32_t addr) {
    asm volatile("ldmatrix.sync.aligned.m8n8.x4.shared.b16 {%0,%1,%2,%3}, [%4];"
                 : "=r"(r0), "=r"(r1), "=r"(r2), "=r"(r3) : "r"(addr));
}
__device__ __forceinline__ void mma16816(float& c0, float& c1, float& c2, float& c3,
                                         uint32_t a0, uint32_t a1, uint32_t a2, uint32_t a3,
                                         uint32_t b0, uint32_t b1) {
    asm volatile("mma.sync.aligned.m16n8k16.row.col.f32.bf16.bf16.f32 "
                 "{%0,%1,%2,%3}, {%4,%5,%6,%7}, {%8,%9}, {%0,%1,%2,%3};"
                 : "+f"(c0), "+f"(c1), "+f"(c2), "+f"(c3)
                 : "r"(a0), "r"(a1), "r"(a2), "r"(a3), "r"(b0), "r"(b1));
}

// FROZEN per-half barrier (R15 best). Do not modify.
__device__ __forceinline__ void gsync(unsigned& gen, unsigned* ctr) {
    __syncthreads();
    if (threadIdx.x == 0) {
        __threadfence();
        atomicAdd(ctr, 1u);
        unsigned target = (gen + 1u) * (unsigned)NBH;
        unsigned v;
        do {
            asm volatile("ld.acquire.gpu.u32 %0, [%1];" : "=r"(v) : "l"(ctr) : "memory");
            if (v < target) __nanosleep(32);
        } while (v < target);
    }
    gen++;
    __syncthreads();
}
__global__ void k_zero() { g_bar2[0] = 0u; g_bar2[32] = 0u; }

// ---------------- prep kernels ----------------
__global__ void k_embed(const int* __restrict__ tokens, const float* __restrict__ embed_w,
                        float* __restrict__ feat) {
    int bt = blockIdx.x;
    int tok = tokens[bt];
    const float4* src = reinterpret_cast<const float4*>(embed_w + (size_t)tok * E_);
    float4* dst = reinterpret_cast<float4*>(feat + (size_t)bt * FEATW);
    dst[threadIdx.x] = src[threadIdx.x];
}

__global__ __launch_bounds__(512) void k_bridge(const unsigned char* __restrict__ mask,
                                                const float* __restrict__ enc_out,
                                                const float* __restrict__ Wb,
                                                const float* __restrict__ bb,
                                                float* __restrict__ hT4) {
    int b = blockIdx.x;
    int j = threadIdx.x;
    __shared__ float fn[512];
    __shared__ int sL;
    if (j == 0) {
        int L = S_;
        for (int s = 0; s < S_; s++) if (mask[b * S_ + s]) L--;
        sL = L;
    }
    __syncthreads();
    int L = sL;
    fn[j] = enc_out[((size_t)(L - 1) * B_ + b) * U_ + j];
    __syncthreads();
    float acc = bb[j];
    const float* wr = Wb + (size_t)j * 512;
    for (int k = 0; k < 512; k++) acc += fn[k] * wr[k];
    hT4[(j >> 2) * 128 + b * 4 + (j & 3)] = tanhf(acc);
}

__global__ void k_transpose(const float* __restrict__ W, float* __restrict__ WT, int R, int C) {
    int idx = blockIdx.x * 256 + threadIdx.x;
    if (idx >= R * C) return;
    int n = idx / C, k = idx % C;
    WT[(size_t)k * R + n] = W[idx];
}

// warp-per-output reductions (fix latency-bound 6/2-block launches)
__global__ void k_bfx2(const float* __restrict__ g2Wx, const float* __restrict__ bf,
                       const float* __restrict__ g2bx, float* __restrict__ bfx2) {
    int g = blockIdx.x * 8 + (threadIdx.x >> 5);
    int lane = threadIdx.x & 31;
    if (g >= 1536) return;
    const float4* w4 = reinterpret_cast<const float4*>(g2Wx + (size_t)g * 1024);
    const float4* b4 = reinterpret_cast<const float4*>(bf);
    float a = 0.f;
    for (int k = lane; k < 256; k += 32) {
        float4 w = w4[k], b = b4[k];
        a += w.x * b.x + w.y * b.y + w.z * b.z + w.w * b.w;
    }
#pragma unroll
    for (int o = 16; o; o >>= 1) a += __shfl_xor_sync(0xffffffffu, a, o);
    if (lane == 0) bfx2[g] = a + g2bx[g];
}
__global__ void k_bo2(const float* __restrict__ Wo, const float* __restrict__ bf,
                      const float* __restrict__ bo, float* __restrict__ bo2) {
    int e = blockIdx.x * 8 + (threadIdx.x >> 5);
    int lane = threadIdx.x & 31;
    if (e >= 512) return;
    const float4* w4 = reinterpret_cast<const float4*>(Wo + (size_t)e * 2048 + 1024);
    const float4* b4 = reinterpret_cast<const float4*>(bf);
    float a = 0.f;
    for (int k = lane; k < 256; k += 32) {
        float4 w = w4[k], b = b4[k];
        a += w.x * b.x + w.y * b.y + w.z * b.z + w.w * b.w;
    }
#pragma unroll
    for (int o = 16; o; o >>= 1) a += __shfl_xor_sync(0xffffffffu, a, o);
    if (lane == 0) bo2[e] = a + bo[e];
}

__global__ void k_wopack(const float* __restrict__ Wo, const float* __restrict__ Wo2f,
                         float* __restrict__ Wp) {
    int idx = blockIdx.x * 256 + threadIdx.x;
    if (idx >= 512 * 2048) return;
    int e = idx >> 11, c = idx & 2047;
    Wp[idx] = (c < 1024) ? Wo[(size_t)e * 2048 + c] : Wo2f[(size_t)e * 1024 + (c - 1024)];
}

// fp32 [R,2048] -> bf16 hi/lo K-extended [R,6144]; kindB=0: [h|h|l] (A-side), 1: [h|l|h] (B-side)
__global__ void k_convHL(const float* __restrict__ F, __nv_bfloat16* __restrict__ A,
                         int R, int kindB) {
    int idx = blockIdx.x * 256 + threadIdx.x;
    if (idx >= R * 512) return;
    int m = idx >> 9, kg = (idx & 511) << 2;
    float4 v = *reinterpret_cast<const float4*>(F + (size_t)m * 2048 + kg);
    __nv_bfloat16 h[4], l[4];
    float x[4] = {v.x, v.y, v.z, v.w};
#pragma unroll
    for (int i = 0; i < 4; i++) {
        h[i] = __float2bfloat16(x[i]);
        l[i] = __float2bfloat16(x[i] - __bfloat162float(h[i]));
    }
    __nv_bfloat162 hh0(h[0], h[1]), hh1(h[2], h[3]);
    __nv_bfloat162 ll0(l[0], l[1]), ll1(l[2], l[3]);
    __nv_bfloat162* p0 = reinterpret_cast<__nv_bfloat162*>(A + (size_t)m * 6144 + kg);
    __nv_bfloat162* p1 = reinterpret_cast<__nv_bfloat162*>(A + (size_t)m * 6144 + 2048 + kg);
    __nv_bfloat162* p2 = reinterpret_cast<__nv_bfloat162*>(A + (size_t)m * 6144 + 4096 + kg);
    p0[0] = hh0; p0[1] = hh1;
    if (kindB) { p1[0] = ll0; p1[1] = ll1; p2[0] = hh0; p2[1] = hh1; }
    else       { p1[0] = hh0; p1[1] = hh1; p2[0] = ll0; p2[1] = ll1; }
}

// ---------------- tiled SGEMM-NT with lda ----------------
#define BM 128
#define BN 128
#define BKk 16
__global__ __launch_bounds__(256) void sgemm_nt(const float* __restrict__ A,
                                                const float* __restrict__ Bm,
                                                const float* __restrict__ bias,
                                                float* __restrict__ C,
                                                int M, int N, int K, int lda, int mode) {
    __shared__ float As[BKk][BM];
    __shared__ float Bs[BKk][BN];
    const int bm = blockIdx.y * BM, bn = blockIdx.x * BN;
    const int tid = threadIdx.x;
    const int tm = (tid >> 4) << 3;
    const int tn = (tid & 15) << 3;
    float acc[8][8];
#pragma unroll
    for (int i = 0; i < 8; i++)
#pragma unroll
        for (int j = 0; j < 8; j++) acc[i][j] = 0.f;

    for (int k0 = 0; k0 < K; k0 += BKk) {
#pragma unroll
        for (int i = 0; i < 2; i++) {
            int idx = tid + i * 256;
            int r = idx >> 2, c = (idx & 3) << 2;
            float4 v = *reinterpret_cast<const float4*>(A + (size_t)(bm + r) * lda + k0 + c);
            As[c][r] = v.x; As[c + 1][r] = v.y; As[c + 2][r] = v.z; As[c + 3][r] = v.w;
            float4 w = *reinterpret_cast<const float4*>(Bm + (size_t)(bn + r) * K + k0 + c);
            Bs[c][r] = w.x; Bs[c + 1][r] = w.y; Bs[c + 2][r] = w.z; Bs[c + 3][r] = w.w;
        }
        __syncthreads();
#pragma unroll
        for (int k = 0; k < BKk; k++) {
            float a[8], bb[8];
            *reinterpret_cast<float4*>(&a[0]) = *reinterpret_cast<const float4*>(&As[k][tm]);
            *reinterpret_cast<float4*>(&a[4]) = *reinterpret_cast<const float4*>(&As[k][tm + 4]);
            *reinterpret_cast<float4*>(&bb[0]) = *reinterpret_cast<const float4*>(&Bs[k][tn]);
            *reinterpret_cast<float4*>(&bb[4]) = *reinterpret_cast<const float4*>(&Bs[k][tn + 4]);
#pragma unroll
            for (int i = 0; i < 8; i++)
#pragma unroll
                for (int j = 0; j < 8; j++) acc[i][j] += a[i] * bb[j];
        }
        __syncthreads();
    }
#pragma unroll
    for (int i = 0; i < 8; i++) {
        int m = bm + tm + i;
#pragma unroll
        for (int j = 0; j < 8; j++) {
            int n = bn + tn + j;
            float v = acc[i][j];
            if (bias) v += bias[n];
            if (mode == 1) v = tanhf(v);
            if (mode == 2) {
                int s_ = m >> 5, b_ = m & 31, nh_ = n >> 6, d_ = n & 63;
                C[(((size_t)(b_ * 8 + nh_) * 64) + s_) * 64 + d_] = v;
            } else if (mode == 3) {
                int b_ = m >> 6, t_ = m & 63;
                C[((size_t)t_ * 1536 + n) * 32 + b_] = v;
            } else {
                C[(size_t)m * N + n] = v;
            }
        }
    }
}

// ---------------- persistent recurrence (R15 frozen) ----------------
#define PERS_SMEM (51200 * 4)

__global__ __launch_bounds__(512, 1)
void k_persistent(const float* __restrict__ X1T, const float* __restrict__ g1Wh,
                  const float* __restrict__ g1bh,
                  const float* __restrict__ Wfx2, const float* __restrict__ bfx2,
                  const float* __restrict__ g2Wh, const float* __restrict__ g2bh,
                  const float* __restrict__ WqT, const float* __restrict__ bq,
                  const float* __restrict__ Ww, const float* __restrict__ bw,
                  const float* __restrict__ enc_out, const unsigned char* __restrict__ mask,
                  const float* __restrict__ keyup,
                  float* __restrict__ feat, float* __restrict__ hT4,
                  float* __restrict__ t4, float* __restrict__ c4) {
    extern __shared__ float sm[];
    float* W1s  = sm;
    float* W2xs = sm + 12288;
    float* W2hs = sm + 36864;
    float* scr  = sm + 49152;
    const int bid = blockIdx.x, tid = threadIdx.x;
    unsigned gen = 0;
    const int bl = tid & 15, jl = (tid >> 4) & 7, q = tid >> 7;
    const int jb = bid >> 1, bh = bid & 1;
    const int j0 = jb * 8, b0 = bh * 16;
    unsigned* ctr = &g_bar2[bh * 32];

    {
        float4* d1 = reinterpret_cast<float4*>(W1s);
        for (int i = tid; i < 3072; i += 512) {
            int jj = i / 384, rem = i % 384, g = rem >> 7, k4 = rem & 127;
            d1[i] = *reinterpret_cast<const float4*>(
                g1Wh + ((size_t)(g * 512 + j0 + jj)) * 512 + k4 * 4);
        }
        float4* d2 = reinterpret_cast<float4*>(W2xs);
        for (int i = tid; i < 6144; i += 512) {
            int jj = i / 768, rem = i % 768, g = rem >> 8, k4 = rem & 255;
            d2[i] = *reinterpret_cast<const float4*>(
                Wfx2 + ((size_t)(g * 512 + j0 + jj)) * 1024 + k4 * 4);
        }
        float4* d3 = reinterpret_cast<float4*>(W2hs);
        for (int i = tid; i < 3072; i += 512) {
            int jj = i / 384, rem = i % 384, g = rem >> 7, k4 = rem & 127;
            d3[i] = *reinterpret_cast<const float4*>(
                g2Wh + ((size_t)(g * 512 + j0 + jj)) * 512 + k4 * 4);
        }
    }
    __syncthreads();

    float h_r, h_z, h_hn;

    for (int t = 0; t < T_; t++) {
        // P1
        float ar = 0.f, az = 0.f, an = 0.f;
        {
            const float4* xp = reinterpret_cast<const float4*>(hT4) + q * 1024 + b0 + bl;
            const float4* wr4 = reinterpret_cast<const float4*>(W1s + (jl * 3 + 0) * 512) + q * 32;
            const float4* wz4 = reinterpret_cast<const float4*>(W1s + (jl * 3 + 1) * 512) + q * 32;
            const float4* wn4 = reinterpret_cast<const float4*>(W1s + (jl * 3 + 2) * 512) + q * 32;
#pragma unroll 8
            for (int kk = 0; kk < 32; kk++) {
                float4 x = __ldcg(xp + kk * 32);
                float4 wr = wr4[kk], wz = wz4[kk], wn = wn4[kk];
                ar += x.x * wr.x + x.y * wr.y + x.z * wr.z + x.w * wr.w;
                az += x.x * wz.x + x.y * wz.y + x.z * wz.z + x.w * wz.w;
                an += x.x * wn.x + x.y * wn.y + x.z * wn.z + x.w * wn.w;
            }
            if (q) {
                int o = (q - 1) * 384 + (jl * 16 + bl) * 3;
                scr[o] = ar; scr[o + 1] = az; scr[o + 2] = an;
            }
        }
        __syncthreads();
        if (q == 0) {
            int o = (jl * 16 + bl) * 3;
            ar += scr[o] + scr[384 + o] + scr[768 + o];
            az += scr[o + 1] + scr[384 + o + 1] + scr[768 + o + 1];
            an += scr[o + 2] + scr[384 + o + 2] + scr[768 + o + 2];
            int j = j0 + jl, b = b0 + bl;
            const float* X1 = X1T + ((size_t)t * 1536) * 32;
            float xr = X1[(size_t)j * 32 + b];
            float xz = X1[(size_t)(512 + j) * 32 + b];
            float xn = X1[(size_t)(1024 + j) * 32 + b];
            float r = 1.f / (1.f + expf(-(xr + g1bh[j] + ar)));
            float z = 1.f / (1.f + expf(-(xz + g1bh[512 + j] + az)));
            float n = tanhf(xn + r * (an + g1bh[1024 + j]));
            float hp = __ldcg(hT4 + (j >> 2) * 128 + b * 4 + (j & 3));
            float o2 = (1.f - z) * n + z * hp;
            t4[(j >> 2) * 128 + b * 4 + (j & 3)] = o2;
        }
        gsync(gen, ctr);

        // P2 (half-local pairs) + GRU2 h-part
        {
            int pr = tid >> 8, tid2 = tid & 255;
            int p_local = (bid & ~1) + pr;
            int b = b0 + (p_local >> 3), nh = p_local & 7;
            float* st  = scr + pr * 512;
            float* sq  = scr + 1024 + pr * 64;
            float* sa  = scr + 1152 + pr * 64;
            float* qp  = scr + 1280 + pr * 256;
            float* scp = scr + 1792 + pr * 128;
            for (int i = tid2; i < 512; i += 256)
                st[i] = __ldcg(t4 + (i >> 2) * 128 + b * 4 + (i & 3));
            __syncthreads();
            {
                int d = tid2 & 63, kq = tid2 >> 6;
                float a = 0.f;
                const float* wp = WqT + nh * 64 + d;
                int k0 = kq * 128;
#pragma unroll 16
                for (int k = k0; k < k0 + 128; k++) a += st[k] * wp[(size_t)k * 512];
                qp[kq * 64 + d] = a;
            }
            __syncthreads();
            if (tid2 < 64)
                sq[tid2] = bq[nh * 64 + tid2] + qp[tid2] + qp[64 + tid2] + qp[128 + tid2] + qp[192 + tid2];
            __syncthreads();
            if (tid2 < 128) {
                int s = tid2 & 63, dh = tid2 >> 6;
                float a = 0.f;
                const float* kp = keyup + (((size_t)(b * 8 + nh)) * 64 + s) * 64 + dh * 32;
                const float* sqh = sq + dh * 32;
                const float* wwh = Ww + dh * 32;
#pragma unroll 8
                for (int d = 0; d < 32; d++) a += tanhf(sqh[d] + kp[d]) * wwh[d];
                scp[dh * 64 + s] = a;
            }
            __syncthreads();
            if (tid2 < 64) {
                float sc = scp[tid2] + scp[64 + tid2] + bw[0];
                if (mask[b * S_ + tid2]) sc -= 1e9f;
                sa[tid2] = sc;
            }
            __syncthreads();
            if (tid2 < 32) {
                float v0 = sa[tid2], v1 = sa[tid2 + 32];
                float mx = fmaxf(v0, v1);
#pragma unroll
                for (int o = 16; o; o >>= 1) mx = fmaxf(mx, __shfl_xor_sync(0xffffffffu, mx, o));
                float e0 = expf(v0 - mx), e1 = expf(v1 - mx);
                float sum = e0 + e1;
#pragma unroll
                for (int o = 16; o; o >>= 1) sum += __shfl_xor_sync(0xffffffffu, sum, o);
                float inv = 1.f / sum;
                sa[tid2] = e0 * inv;
                sa[tid2 + 32] = e1 * inv;
            }
            __syncthreads();
            if (tid2 < 128) {
                float a = 0.f;
                const float* vp = enc_out + (size_t)b * U_ + nh * 128 + tid2;
#pragma unroll
                for (int s = 0; s < 64; s++) a += sa[s] * vp[(size_t)s * B_ * U_];
                int n = nh * 128 + tid2;
                c4[(n >> 2) * 128 + b * 4 + (n & 3)] = a;
                feat[((size_t)b * T_ + t) * FEATW + 1024 + n] = a;
            }
        }
        {
            h_r = 0.f; h_z = 0.f; h_hn = 0.f;
            const float4* xp = reinterpret_cast<const float4*>(t4) + q * 1024 + b0 + bl;
            const float4* wr4 = reinterpret_cast<const float4*>(W2hs + (jl * 3 + 0) * 512) + q * 32;
            const float4* wz4 = reinterpret_cast<const float4*>(W2hs + (jl * 3 + 1) * 512) + q * 32;
            const float4* wn4 = reinterpret_cast<const float4*>(W2hs + (jl * 3 + 2) * 512) + q * 32;
#pragma unroll 8
            for (int kk = 0; kk < 32; kk++) {
                float4 x = __ldcg(xp + kk * 32);
                float4 wr = wr4[kk], wz = wz4[kk], wn = wn4[kk];
                h_r  += x.x * wr.x + x.y * wr.y + x.z * wr.z + x.w * wr.w;
                h_z  += x.x * wz.x + x.y * wz.y + x.z * wz.z + x.w * wz.w;
                h_hn += x.x * wn.x + x.y * wn.y + x.z * wn.z + x.w * wn.w;
            }
        }
        gsync(gen, ctr);

        // P3
        float a_r = h_r, a_z = h_z, a_xn = 0.f, a_hn = h_hn;
        {
            const float4* xp = reinterpret_cast<const float4*>(c4) + q * 2048 + b0 + bl;
            const float4* wr4 = reinterpret_cast<const float4*>(W2xs + (jl * 3 + 0) * 1024) + q * 64;
            const float4* wz4 = reinterpret_cast<const float4*>(W2xs + (jl * 3 + 1) * 1024) + q * 64;
            const float4* wn4 = reinterpret_cast<const float4*>(W2xs + (jl * 3 + 2) * 1024) + q * 64;
#pragma unroll 8
            for (int kk = 0; kk < 64; kk++) {
                float4 x = __ldcg(xp + kk * 32);
                float4 wr = wr4[kk], wz = wz4[kk], wn = wn4[kk];
                a_r  += x.x * wr.x + x.y * wr.y + x.z * wr.z + x.w * wr.w;
                a_z  += x.x * wz.x + x.y * wz.y + x.z * wz.z + x.w * wz.w;
                a_xn += x.x * wn.x + x.y * wn.y + x.z * wn.z + x.w * wn.w;
            }
            if (q) {
                int o = (q - 1) * 512 + (jl * 16 + bl) * 4;
                scr[o] = a_r; scr[o + 1] = a_z; scr[o + 2] = a_xn; scr[o + 3] = a_hn;
            }
        }
        __syncthreads();
        if (q == 0) {
            int o = (jl * 16 + bl) * 4;
            a_r  += scr[o] + scr[512 + o] + scr[1024 + o];
            a_z  += scr[o + 1] + scr[512 + o + 1] + scr[1024 + o + 1];
            a_xn += scr[o + 2] + scr[512 + o + 2] + scr[1024 + o + 2];
            a_hn += scr[o + 3] + scr[512 + o + 3] + scr[1024 + o + 3];
            int j = j0 + jl, b = b0 + bl, m = b * T_ + t;
            float r = 1.f / (1.f + expf(-(a_r + bfx2[j] + g2bh[j])));
            float z = 1.f / (1.f + expf(-(a_z + bfx2[512 + j] + g2bh[512 + j])));
            float n = tanhf(a_xn + bfx2[1024 + j] + r * (a_hn + g2bh[1024 + j]));
            float hp = __ldcg(t4 + (j >> 2) * 128 + b * 4 + (j & 3));
            float o2 = (1.f - z) * n + z * hp;
            hT4[(j >> 2) * 128 + b * 4 + (j & 3)] = o2;
            feat[(size_t)m * FEATW + 512 + j] = o2;
        }
        gsync(gen, ctr);
    }
}

// ============ bf16 hi/lo split for embed_w ============
__global__ void k_convB(const float* __restrict__ W, __nv_bfloat16* __restrict__ Bp) {
    int idx = blockIdx.x * 256 + threadIdx.x;
    if (idx >= 32000 * 128) return;
    int n = idx >> 7, kg = (idx & 127) << 2;
    float4 v = *reinterpret_cast<const float4*>(W + (size_t)n * 512 + kg);
    __nv_bfloat16 h[4], l[4];
    float x[4] = {v.x, v.y, v.z, v.w};
#pragma unroll
    for (int i = 0; i < 4; i++) {
        h[i] = __float2bfloat16(x[i]);
        l[i] = __float2bfloat16(x[i] - __bfloat162float(h[i]));
    }
    __nv_bfloat162* p0 = reinterpret_cast<__nv_bfloat162*>(Bp + (size_t)n * 1536 + kg);
    __nv_bfloat162* p1 = reinterpret_cast<__nv_bfloat162*>(Bp + (size_t)n * 1536 + 512 + kg);
    __nv_bfloat162* p2 = reinterpret_cast<__nv_bfloat162*>(Bp + (size_t)n * 1536 + 1024 + kg);
    p0[0] = __nv_bfloat162(h[0], h[1]); p0[1] = __nv_bfloat162(h[2], h[3]);
    p1[0] = __nv_bfloat162(l[0], l[1]); p1[1] = __nv_bfloat162(l[2], l[3]);
    p2[0] = __nv_bfloat162(h[0], h[1]); p2[1] = __nv_bfloat162(h[2], h[3]);
}

// ============ HMMA bf16 GEMM (final tied projection, K=1536) ============
#define HG_A_BYTES 16384
#define HG_B_BYTES 16384
#define HG_SMEM_TOTAL (2 * (HG_A_BYTES + HG_B_BYTES))

#define HLOADG(s, buf, Ag, Bg, LDA) { \
    uint32_t ab_ = sb_a + (buf) * HG_A_BYTES; \
    uint32_t bb_ = sb_b + (buf) * HG_B_BYTES; \
    const __nv_bfloat16* As_ = (Ag) + (s) * 64; \
    const __nv_bfloat16* Bs_ = (Bg) + (s) * 64; \
    _Pragma("unroll") \
    for (int i_ = 0; i_ < 4; i_++) { int ix_ = tid + i_ * 256; int r_ = ix_ >> 3, c_ = ix_ & 7; \
        cp_async16(ab_ + SW128(r_ * 128 + c_ * 16), As_ + (size_t)r_ * (LDA) + c_ * 8); } \
    _Pragma("unroll") \
    for (int i_ = 0; i_ < 4; i_++) { int ix_ = tid + i_ * 256; int r_ = ix_ >> 3, c_ = ix_ & 7; \
        cp_async16(bb_ + SW128(r_ * 128 + c_ * 16), Bs_ + (size_t)r_ * (LDA) + c_ * 8); } \
    CP_COMMIT(); }

#define HMMA_BODY(NSLAB, Ag, Bg, LDA) \
    float acc[2][8][4]; \
    _Pragma("unroll") \
    for (int i = 0; i < 2; i++) \
        _Pragma("unroll") \
        for (int j = 0; j < 8; j++) \
            _Pragma("unroll") \
            for (int v = 0; v < 4; v++) acc[i][j][v] = 0.f; \
    HLOADG(0, 0, Ag, Bg, LDA); \
    HLOADG(1, 1, Ag, Bg, LDA); \
    const int a_row_off = ((lane >> 3) & 1) * 8 + (lane & 7); \
    const int a_kb_off  = ((lane >> 4) & 1) * 16; \
    const int b_row_off = ((lane >> 4) & 1) * 8 + (lane & 7); \
    const int b_kb_off  = ((lane >> 3) & 1) * 16; \
    for (int s = 0; s < (NSLAB); s++) { \
        int buf = s & 1; \
        CP_WAIT(1); \
        __syncthreads(); \
        uint32_t abase = sb_a + buf * HG_A_BYTES; \
        uint32_t bbase = sb_b + buf * HG_B_BYTES; \
        _Pragma("unroll") \
        for (int kk = 0; kk < 4; kk++) { \
            uint32_t a[2][4]; \
            _Pragma("unroll") \
            for (int mi = 0; mi < 2; mi++) { \
                int row = m0 + mi * 16 + a_row_off; \
                int kb = kk * 32 + a_kb_off; \
                ldsm_x4(a[mi][0], a[mi][1], a[mi][2], a[mi][3], abase + SW128(row * 128 + kb)); \
            } \
            uint32_t bfr[4][4]; \
            _Pragma("unroll") \
            for (int ng = 0; ng < 4; ng++) { \
                int row = n0 + ng * 16 + b_row_off; \
                int kb = kk * 32 + b_kb_off; \
                ldsm_x4(bfr[ng][0], bfr[ng][1], bfr[ng][2], bfr[ng][3], bbase + SW128(row * 128 + kb)); \
            } \
            _Pragma("unroll") \
            for (int mi = 0; mi < 2; mi++) \
                _Pragma("unroll") \
                for (int nj = 0; nj < 8; nj++) { \
                    uint32_t b0 = bfr[nj >> 1][(nj & 1) * 2]; \
                    uint32_t b1 = bfr[nj >> 1][(nj & 1) * 2 + 1]; \
                    mma16816(acc[mi][nj][0], acc[mi][nj][1], acc[mi][nj][2], acc[mi][nj][3], \
                             a[mi][0], a[mi][1], a[mi][2], a[mi][3], b0, b1); \
                } \
        } \
        __syncthreads(); \
        if (s + 2 < (NSLAB)) HLOADG(s + 2, buf, Ag, Bg, LDA); \
    }

__global__ __launch_bounds__(256, 2)
void mma_gemm_hmma(const __nv_bfloat16* __restrict__ Ap, const __nv_bfloat16* __restrict__ Bp,
                   float* __restrict__ C) {
    extern __shared__ char smemc[];
    uint32_t sb_a = smem_to_u32(smemc);
    uint32_t sb_b = sb_a + 2 * HG_A_BYTES;
    const int tid = threadIdx.x, lane = tid & 31, wid = tid >> 5;
    const int mt = blockIdx.y, nt = blockIdx.x;
    const int m0 = (wid & 3) * 32;
    const int n0 = (wid >> 2) * 64;
    const __nv_bfloat16* Ag = Ap + (size_t)mt * 128 * 1536;
    const __nv_bfloat16* Bg = Bp + (size_t)nt * 128 * 1536;

    HMMA_BODY(24, Ag, Bg, 1536)

    int gr = mt * 128 + m0 + (lane >> 2);
    int gc = nt * 128 + n0 + (lane & 3) * 2;
#pragma unroll
    for (int mi = 0; mi < 2; mi++) {
#pragma unroll
        for (int nj = 0; nj < 8; nj++) {
            float* p0 = C + (size_t)(gr + mi * 16) * V_ + gc + nj * 8;
            float* p1 = C + (size_t)(gr + mi * 16 + 8) * V_ + gc + nj * 8;
            *reinterpret_cast<float2*>(p0) = make_float2(acc[mi][nj][0], acc[mi][nj][1]);
            *reinterpret_cast<float2*>(p1) = make_float2(acc[mi][nj][2], acc[mi][nj][3]);
        }
    }
}

// logits HMMA: C = tanh(featHL @ WopkHL^T + bo2) -> Ahl hi/hi/lo (K'=6144, 96 slabs)
__global__ __launch_bounds__(256, 2)
void mma_logits_hmma(const __nv_bfloat16* __restrict__ Ap, const __nv_bfloat16* __restrict__ Bp,
                     const float* __restrict__ bo2, __nv_bfloat16* __restrict__ Ahl) {
    extern __shared__ char smemc[];
    uint32_t sb_a = smem_to_u32(smemc);
    uint32_t sb_b = sb_a + 2 * HG_A_BYTES;
    const int tid = threadIdx.x, lane = tid & 31, wid = tid >> 5;
    const int mt = blockIdx.y, nt = blockIdx.x;
    const int m0 = (wid & 3) * 32;
    const int n0 = (wid >> 2) * 64;
    const __nv_bfloat16* Ag = Ap + (size_t)mt * 128 * 6144;
    const __nv_bfloat16* Bg = Bp + (size_t)nt * 128 * 6144;

    HMMA_BODY(96, Ag, Bg, 6144)

    int gr = mt * 128 + m0 + (lane >> 2);
    int gc = nt * 128 + n0 + (lane & 3) * 2;
#pragma unroll
    for (int mi = 0; mi < 2; mi++) {
#pragma unroll
        for (int half = 0; half < 2; half++) {
            int m = gr + mi * 16 + half * 8;
#pragma unroll
            for (int nj = 0; nj < 8; nj++) {
#pragma unroll
                for (int c = 0; c < 2; c++) {
                    int n = gc + nj * 8 + c;
                    float v = tanhf(acc[mi][nj][half * 2 + c] + bo2[n]);
                    __nv_bfloat16 hi = __float2bfloat16(v);
                    __nv_bfloat16 lo = __float2bfloat16(v - __bfloat162float(hi));
                    Ahl[(size_t)m * 1536 + n] = hi;
                    Ahl[(size_t)m * 1536 + 512 + n] = hi;
                    Ahl[(size_t)m * 1536 + 1024 + n] = lo;
                }
            }
        }
    }
}

// ---------------- host orchestration ----------------
extern "C" void kernel_launch(void* const* d_in, const int* in_sizes, int n_in,
                              void* d_out, int out_size) {
    const int*   tokens  = (const int*)d_in[0];
    const unsigned char* enc_mask = (const unsigned char*)d_in[1];
    const float* enc_out = (const float*)d_in[2];
    const float* embed_w = (const float*)d_in[3];
    const float* g1Wx = (const float*)d_in[4];
    const float* g1Wh = (const float*)d_in[5];
    const float* g1bx = (const float*)d_in[6];
    const float* g1bh = (const float*)d_in[7];
    const float* g2Wx = (const float*)d_in[8];
    const float* g2Wh = (const float*)d_in[9];
    const float* g2bx = (const float*)d_in[10];
    const float* g2bh = (const float*)d_in[11];
    const float* brW  = (const float*)d_in[12];
    const float* brB  = (const float*)d_in[13];
    const float* Wk   = (const float*)d_in[14];
    const float* bk   = (const float*)d_in[15];
    const float* Wq   = (const float*)d_in[16];
    const float* bq   = (const float*)d_in[17];
    const float* Ww   = (const float*)d_in[18];
    const float* bw   = (const float*)d_in[19];
    const float* Wf   = (const float*)d_in[20];
    const float* bf   = (const float*)d_in[21];
    const float* Wo   = (const float*)d_in[22];
    const float* bo   = (const float*)d_in[23];
    float* out = (float*)d_out;

    float* S = nullptr;
    cudaGetSymbolAddress((void**)&S, g_scratch);
    float* feat    = S + OFF_FEAT;
    float* keyup   = S + OFF_KEYUP;
    float* hT4     = S + OFF_HT;
    float* t4      = S + OFF_TMP;
    float* c4      = S + OFF_CTXRT;
    float* X1T     = S + OFF_X1ALL;
    float* Wfx2    = S + OFF_WFX2;
    float* bfx2    = S + OFF_BFX2;
    float* WqT     = S + OFF_WQT;
    float* WfT     = S + OFF_WFT;
    float* Wo2f    = S + OFF_WO2F;
    float* Wopk    = S + OFF_WOPK;
    float* bo2     = S + OFF_BO2;
    __nv_bfloat16* Ahl  = (__nv_bfloat16*)(S + OFF_AHL);
    __nv_bfloat16* Bhl  = (__nv_bfloat16*)(S + OFF_BHL);
    __nv_bfloat16* Fhl  = (__nv_bfloat16*)(S + OFF_FHL);
    __nv_bfloat16* Wohl = (__nv_bfloat16*)(S + OFF_WOHL);

    // ---- prep ----
    k_embed<<<B_ * T_, 128>>>(tokens, embed_w, feat);
    k_bridge<<<B_, 512>>>(enc_mask, enc_out, brW, brB, hT4);
    k_transpose<<<(512 * 512 + 255) / 256, 256>>>(Wq, WqT, 512, 512);
    k_transpose<<<(1024 * 1024 + 255) / 256, 256>>>(Wf, WfT, 1024, 1024);
    k_bfx2<<<192, 256>>>(g2Wx, bf, g2bx, bfx2);
    k_bo2<<<64, 256>>>(Wo, bf, bo, bo2);
    k_convB<<<(32000 * 128 + 255) / 256, 256>>>(embed_w, Bhl);
    {   // keyup = enc @ Wk^T + bk
        dim3 g(512 / BN, 2048 / BM);
        sgemm_nt<<<g, 256>>>(enc_out, Wk, bk, keyup, 2048, 512, 1024, 1024, 2);
    }
    {   // X1T = emb @ g1Wx^T + g1bx, stored [t][j][b]
        dim3 g(1536 / BN, 2048 / BM);
        sgemm_nt<<<g, 256>>>(feat, g1Wx, g1bx, X1T, 2048, 1536, 512, 2048, 3);
    }
    {   // Wfx2 = g2Wx (x) Wf
        dim3 g(1024 / BN, 1536 / BM);
        sgemm_nt<<<g, 256>>>(g2Wx, WfT, nullptr, Wfx2, 1536, 1024, 1024, 1024, 0);
    }
    {   // Wo2f[e][n] = sum_m Wo[e][1024+m] Wf[m][n]
        dim3 g(1024 / BN, 512 / BM);
        sgemm_nt<<<g, 256>>>(Wo + 1024, WfT, nullptr, Wo2f, 512, 1024, 1024, 2048, 0);
    }
    k_wopack<<<(512 * 2048 + 255) / 256, 256>>>(Wo, Wo2f, Wopk);
    k_convHL<<<(512 * 512 + 255) / 256, 256>>>(Wopk, Wohl, 512, 1);   // B-side [h|l|h]

    // ---- persistent recurrence ----
    k_zero<<<1, 1>>>();
    cudaFuncSetAttribute(k_persistent, cudaFuncAttributeMaxDynamicSharedMemorySize, PERS_SMEM);
    k_persistent<<<NB, 512, PERS_SMEM>>>(X1T, g1Wh, g1bh, Wfx2, bfx2, g2Wh, g2bh,
                                         WqT, bq, Ww, bw,
                                         enc_out, enc_mask, keyup,
                                         feat, hT4, t4, c4);

    // ---- tail: logits via HMMA hi/lo, then tied projection ----
    k_convHL<<<(2048 * 512 + 255) / 256, 256>>>(feat, Fhl, 2048, 0);  // A-side [h|h|l]
    cudaFuncSetAttribute(mma_logits_hmma, cudaFuncAttributeMaxDynamicSharedMemorySize, HG_SMEM_TOTAL);
    {
        dim3 g(512 / 128, 2048 / 128);
        mma_logits_hmma<<<g, 256, HG_SMEM_TOTAL>>>(Fhl, Wohl, bo2, Ahl);
    }
    cudaFuncSetAttribute(mma_gemm_hmma, cudaFuncAttributeMaxDynamicSharedMemorySize, HG_SMEM_TOTAL);
    {
        dim3 g(V_ / 128, 2048 / 128);
        mma_gemm_hmma<<<g, 256, HG_SMEM_TOTAL>>>(Ahl, Bhl, out);
    }
}

// round 17
// speedup vs baseline: 1.5240x; 1.1398x over previous
#include <cuda_runtime.h>
#include <cuda_bf16.h>
#include <math.h>
#include <stdint.h>

#define B_ 32
#define T_ 64
#define S_ 64
#define V_ 32000
#define E_ 512
#define H_ 512
#define U_ 1024
#define NH_ 8
#define FEATW 2048
#define NB 128
#define NBH 64

// ---------------- scratch offsets (floats) ----------------
#define OFF_FEAT   0ull
#define OFF_KEYUP  4194304ull
#define OFF_LOGITS 5242880ull
#define OFF_HT     6291456ull
#define OFF_TMP    6307840ull
#define OFF_CTXRT  6340608ull
#define OFF_X1ALL  6373376ull
#define OFF_WFX2   9519104ull
#define OFF_BFX2   11091968ull
#define OFF_WQT    11094016ull
#define OFF_WFT    11356160ull
#define OFF_WO2F   12404736ull
#define OFF_WOPK   12929024ull
#define OFF_BO2    13977600ull
#define OFF_AHL    13978624ull    // [2048,1536] bf16
#define OFF_BHL    15551488ull    // [32000,1536] bf16
#define OFF_FHL    40127488ull    // [2048,6144] bf16
#define OFF_WOHL   46418944ull    // [512,6144] bf16
#define OFF_ENCHL  47991808ull    // [2048,3072] bf16
#define OFF_WKHL   51137536ull    // [512,3072] bf16
#define OFF_EMBHL  51923968ull    // [2048,1536] bf16
#define OFF_G1WXHL 53496832ull    // [1536,1536] bf16
#define OFF_G2WXHL 54676480ull    // [1536,3072] bf16
#define OFF_WFTHL  57035776ull    // [1024,3072] bf16
#define OFF_WOAHL  58608640ull    // [512,3072] bf16
#define SCRATCH_FLOATS 59395072ull

__device__ float g_scratch[SCRATCH_FLOATS];
__device__ unsigned g_bar2[64];

__device__ __forceinline__ uint32_t smem_to_u32(const void* p) {
    uint32_t a;
    asm("{ .reg .u64 t; cvta.to.shared.u64 t, %1; cvt.u32.u64 %0, t; }" : "=r"(a) : "l"(p));
    return a;
}
__device__ __forceinline__ void cp_async16(uint32_t dst, const void* src) {
    asm volatile("cp.async.cg.shared.global [%0], [%1], 16;" :: "r"(dst), "l"(src));
}
#define CP_COMMIT() asm volatile("cp.async.commit_group;" ::: "memory")
#define CP_WAIT(n)  asm volatile("cp.async.wait_group %0;" :: "n"(n) : "memory")
#define SW128(x) ((x) ^ (((x) >> 3) & 0x70))

__device__ __forceinline__ void ldsm_x4(uint32_t& r0, uint32_t& r1, uint32_t& r2, uint32_t& r3,
                                        uint32_t addr) {
    asm volatile("ldmatrix.sync.aligned.m8n8.x4.shared.b16 {%0,%1,%2,%3}, [%4];"
                 : "=r"(r0), "=r"(r1), "=r"(r2), "=r"(r3) : "r"(addr));
}
__device__ __forceinline__ void mma16816(float& c0, float& c1, float& c2, float& c3,
                                         uint32_t a0, uint32_t a1, uint32_t a2, uint32_t a3,
                                         uint32_t b0, uint32_t b1) {
    asm volatile("mma.sync.aligned.m16n8k16.row.col.f32.bf16.bf16.f32 "
                 "{%0,%1,%2,%3}, {%4,%5,%6,%7}, {%8,%9}, {%0,%1,%2,%3};"
                 : "+f"(c0), "+f"(c1), "+f"(c2), "+f"(c3)
                 : "r"(a0), "r"(a1), "r"(a2), "r"(a3), "r"(b0), "r"(b1));
}

// FROZEN per-half barrier (R15 best). Do not modify.
__device__ __forceinline__ void gsync(unsigned& gen, unsigned* ctr) {
    __syncthreads();
    if (threadIdx.x == 0) {
        __threadfence();
        atomicAdd(ctr, 1u);
        unsigned target = (gen + 1u) * (unsigned)NBH;
        unsigned v;
        do {
            asm volatile("ld.acquire.gpu.u32 %0, [%1];" : "=r"(v) : "l"(ctr) : "memory");
            if (v < target) __nanosleep(32);
        } while (v < target);
    }
    gen++;
    __syncthreads();
}
__global__ void k_zero() { g_bar2[0] = 0u; g_bar2[32] = 0u; }

// ---------------- prep kernels ----------------
__global__ void k_embed(const int* __restrict__ tokens, const float* __restrict__ embed_w,
                        float* __restrict__ feat) {
    int bt = blockIdx.x;
    int tok = tokens[bt];
    const float4* src = reinterpret_cast<const float4*>(embed_w + (size_t)tok * E_);
    float4* dst = reinterpret_cast<float4*>(feat + (size_t)bt * FEATW);
    dst[threadIdx.x] = src[threadIdx.x];
}

__global__ __launch_bounds__(512) void k_bridge(const unsigned char* __restrict__ mask,
                                                const float* __restrict__ enc_out,
                                                const float* __restrict__ Wb,
                                                const float* __restrict__ bb,
                                                float* __restrict__ hT4) {
    int b = blockIdx.x;
    int j = threadIdx.x;
    __shared__ float fn[512];
    __shared__ int sL;
    if (j == 0) {
        int L = S_;
        for (int s = 0; s < S_; s++) if (mask[b * S_ + s]) L--;
        sL = L;
    }
    __syncthreads();
    int L = sL;
    fn[j] = enc_out[((size_t)(L - 1) * B_ + b) * U_ + j];
    __syncthreads();
    float acc = bb[j];
    const float* wr = Wb + (size_t)j * 512;
    for (int k = 0; k < 512; k++) acc += fn[k] * wr[k];
    hT4[(j >> 2) * 128 + b * 4 + (j & 3)] = tanhf(acc);
}

__global__ void k_transpose(const float* __restrict__ W, float* __restrict__ WT, int R, int C) {
    int idx = blockIdx.x * 256 + threadIdx.x;
    if (idx >= R * C) return;
    int n = idx / C, k = idx % C;
    WT[(size_t)k * R + n] = W[idx];
}

__global__ void k_bfx2(const float* __restrict__ g2Wx, const float* __restrict__ bf,
                       const float* __restrict__ g2bx, float* __restrict__ bfx2) {
    int g = blockIdx.x * 8 + (threadIdx.x >> 5);
    int lane = threadIdx.x & 31;
    if (g >= 1536) return;
    const float4* w4 = reinterpret_cast<const float4*>(g2Wx + (size_t)g * 1024);
    const float4* b4 = reinterpret_cast<const float4*>(bf);
    float a = 0.f;
    for (int k = lane; k < 256; k += 32) {
        float4 w = w4[k], b = b4[k];
        a += w.x * b.x + w.y * b.y + w.z * b.z + w.w * b.w;
    }
#pragma unroll
    for (int o = 16; o; o >>= 1) a += __shfl_xor_sync(0xffffffffu, a, o);
    if (lane == 0) bfx2[g] = a + g2bx[g];
}
__global__ void k_bo2(const float* __restrict__ Wo, const float* __restrict__ bf,
                      const float* __restrict__ bo, float* __restrict__ bo2) {
    int e = blockIdx.x * 8 + (threadIdx.x >> 5);
    int lane = threadIdx.x & 31;
    if (e >= 512) return;
    const float4* w4 = reinterpret_cast<const float4*>(Wo + (size_t)e * 2048 + 1024);
    const float4* b4 = reinterpret_cast<const float4*>(bf);
    float a = 0.f;
    for (int k = lane; k < 256; k += 32) {
        float4 w = w4[k], b = b4[k];
        a += w.x * b.x + w.y * b.y + w.z * b.z + w.w * b.w;
    }
#pragma unroll
    for (int o = 16; o; o >>= 1) a += __shfl_xor_sync(0xffffffffu, a, o);
    if (lane == 0) bo2[e] = a + bo[e];
}

__global__ void k_wopack(const float* __restrict__ Wo, const float* __restrict__ Wo2f,
                         float* __restrict__ Wp) {
    int idx = blockIdx.x * 256 + threadIdx.x;
    if (idx >= 512 * 2048) return;
    int e = idx >> 11, c = idx & 2047;
    Wp[idx] = (c < 1024) ? Wo[(size_t)e * 2048 + c] : Wo2f[(size_t)e * 1024 + (c - 1024)];
}

// fp32 [R,2048] -> bf16 hi/lo [R,6144] (tail path)
__global__ void k_convHL(const float* __restrict__ F, __nv_bfloat16* __restrict__ A,
                         int R, int kindB) {
    int idx = blockIdx.x * 256 + threadIdx.x;
    if (idx >= R * 512) return;
    int m = idx >> 9, kg = (idx & 511) << 2;
    float4 v = *reinterpret_cast<const float4*>(F + (size_t)m * 2048 + kg);
    __nv_bfloat16 h[4], l[4];
    float x[4] = {v.x, v.y, v.z, v.w};
#pragma unroll
    for (int i = 0; i < 4; i++) {
        h[i] = __float2bfloat16(x[i]);
        l[i] = __float2bfloat16(x[i] - __bfloat162float(h[i]));
    }
    __nv_bfloat162 hh0(h[0], h[1]), hh1(h[2], h[3]);
    __nv_bfloat162 ll0(l[0], l[1]), ll1(l[2], l[3]);
    __nv_bfloat162* p0 = reinterpret_cast<__nv_bfloat162*>(A + (size_t)m * 6144 + kg);
    __nv_bfloat162* p1 = reinterpret_cast<__nv_bfloat162*>(A + (size_t)m * 6144 + 2048 + kg);
    __nv_bfloat162* p2 = reinterpret_cast<__nv_bfloat162*>(A + (size_t)m * 6144 + 4096 + kg);
    p0[0] = hh0; p0[1] = hh1;
    if (kindB) { p1[0] = ll0; p1[1] = ll1; p2[0] = hh0; p2[1] = hh1; }
    else       { p1[0] = hh0; p1[1] = hh1; p2[0] = ll0; p2[1] = ll1; }
}

// generic fp32 [R,K] (row-stride ld) -> bf16 hi/lo [R,3K]; kindB 0:[h|h|l] 1:[h|l|h]
__global__ void k_convHLG(const float* __restrict__ F, __nv_bfloat16* __restrict__ A,
                          int R, int K, int ld, int kindB) {
    int kg4 = K >> 2;
    int idx = blockIdx.x * 256 + threadIdx.x;
    if (idx >= R * kg4) return;
    int m = idx / kg4, kg = (idx % kg4) << 2;
    float4 v = *reinterpret_cast<const float4*>(F + (size_t)m * ld + kg);
    __nv_bfloat16 h[4], l[4];
    float x[4] = {v.x, v.y, v.z, v.w};
#pragma unroll
    for (int i = 0; i < 4; i++) {
        h[i] = __float2bfloat16(x[i]);
        l[i] = __float2bfloat16(x[i] - __bfloat162float(h[i]));
    }
    __nv_bfloat162 hh0(h[0], h[1]), hh1(h[2], h[3]);
    __nv_bfloat162 ll0(l[0], l[1]), ll1(l[2], l[3]);
    size_t base = (size_t)m * 3 * K;
    __nv_bfloat162* p0 = reinterpret_cast<__nv_bfloat162*>(A + base + kg);
    __nv_bfloat162* p1 = reinterpret_cast<__nv_bfloat162*>(A + base + K + kg);
    __nv_bfloat162* p2 = reinterpret_cast<__nv_bfloat162*>(A + base + 2 * K + kg);
    p0[0] = hh0; p0[1] = hh1;
    if (kindB) { p1[0] = ll0; p1[1] = ll1; p2[0] = hh0; p2[1] = hh1; }
    else       { p1[0] = hh0; p1[1] = hh1; p2[0] = ll0; p2[1] = ll1; }
}

// ---------------- persistent recurrence (R15 frozen) ----------------
#define PERS_SMEM (51200 * 4)

__global__ __launch_bounds__(512, 1)
void k_persistent(const float* __restrict__ X1T, const float* __restrict__ g1Wh,
                  const float* __restrict__ g1bh,
                  const float* __restrict__ Wfx2, const float* __restrict__ bfx2,
                  const float* __restrict__ g2Wh, const float* __restrict__ g2bh,
                  const float* __restrict__ WqT, const float* __restrict__ bq,
                  const float* __restrict__ Ww, const float* __restrict__ bw,
                  const float* __restrict__ enc_out, const unsigned char* __restrict__ mask,
                  const float* __restrict__ keyup,
                  float* __restrict__ feat, float* __restrict__ hT4,
                  float* __restrict__ t4, float* __restrict__ c4) {
    extern __shared__ float sm[];
    float* W1s  = sm;
    float* W2xs = sm + 12288;
    float* W2hs = sm + 36864;
    float* scr  = sm + 49152;
    const int bid = blockIdx.x, tid = threadIdx.x;
    unsigned gen = 0;
    const int bl = tid & 15, jl = (tid >> 4) & 7, q = tid >> 7;
    const int jb = bid >> 1, bh = bid & 1;
    const int j0 = jb * 8, b0 = bh * 16;
    unsigned* ctr = &g_bar2[bh * 32];

    {
        float4* d1 = reinterpret_cast<float4*>(W1s);
        for (int i = tid; i < 3072; i += 512) {
            int jj = i / 384, rem = i % 384, g = rem >> 7, k4 = rem & 127;
            d1[i] = *reinterpret_cast<const float4*>(
                g1Wh + ((size_t)(g * 512 + j0 + jj)) * 512 + k4 * 4);
        }
        float4* d2 = reinterpret_cast<float4*>(W2xs);
        for (int i = tid; i < 6144; i += 512) {
            int jj = i / 768, rem = i % 768, g = rem >> 8, k4 = rem & 255;
            d2[i] = *reinterpret_cast<const float4*>(
                Wfx2 + ((size_t)(g * 512 + j0 + jj)) * 1024 + k4 * 4);
        }
        float4* d3 = reinterpret_cast<float4*>(W2hs);
        for (int i = tid; i < 3072; i += 512) {
            int jj = i / 384, rem = i % 384, g = rem >> 7, k4 = rem & 127;
            d3[i] = *reinterpret_cast<const float4*>(
                g2Wh + ((size_t)(g * 512 + j0 + jj)) * 512 + k4 * 4);
        }
    }
    __syncthreads();

    float h_r, h_z, h_hn;

    for (int t = 0; t < T_; t++) {
        // P1
        float ar = 0.f, az = 0.f, an = 0.f;
        {
            const float4* xp = reinterpret_cast<const float4*>(hT4) + q * 1024 + b0 + bl;
            const float4* wr4 = reinterpret_cast<const float4*>(W1s + (jl * 3 + 0) * 512) + q * 32;
            const float4* wz4 = reinterpret_cast<const float4*>(W1s + (jl * 3 + 1) * 512) + q * 32;
            const float4* wn4 = reinterpret_cast<const float4*>(W1s + (jl * 3 + 2) * 512) + q * 32;
#pragma unroll 8
            for (int kk = 0; kk < 32; kk++) {
                float4 x = __ldcg(xp + kk * 32);
                float4 wr = wr4[kk], wz = wz4[kk], wn = wn4[kk];
                ar += x.x * wr.x + x.y * wr.y + x.z * wr.z + x.w * wr.w;
                az += x.x * wz.x + x.y * wz.y + x.z * wz.z + x.w * wz.w;
                an += x.x * wn.x + x.y * wn.y + x.z * wn.z + x.w * wn.w;
            }
            if (q) {
                int o = (q - 1) * 384 + (jl * 16 + bl) * 3;
                scr[o] = ar; scr[o + 1] = az; scr[o + 2] = an;
            }
        }
        __syncthreads();
        if (q == 0) {
            int o = (jl * 16 + bl) * 3;
            ar += scr[o] + scr[384 + o] + scr[768 + o];
            az += scr[o + 1] + scr[384 + o + 1] + scr[768 + o + 1];
            an += scr[o + 2] + scr[384 + o + 2] + scr[768 + o + 2];
            int j = j0 + jl, b = b0 + bl;
            const float* X1 = X1T + ((size_t)t * 1536) * 32;
            float xr = X1[(size_t)j * 32 + b];
            float xz = X1[(size_t)(512 + j) * 32 + b];
            float xn = X1[(size_t)(1024 + j) * 32 + b];
            float r = 1.f / (1.f + expf(-(xr + g1bh[j] + ar)));
            float z = 1.f / (1.f + expf(-(xz + g1bh[512 + j] + az)));
            float n = tanhf(xn + r * (an + g1bh[1024 + j]));
            float hp = __ldcg(hT4 + (j >> 2) * 128 + b * 4 + (j & 3));
            float o2 = (1.f - z) * n + z * hp;
            t4[(j >> 2) * 128 + b * 4 + (j & 3)] = o2;
        }
        gsync(gen, ctr);

        // P2 (half-local pairs) + GRU2 h-part
        {
            int pr = tid >> 8, tid2 = tid & 255;
            int p_local = (bid & ~1) + pr;
            int b = b0 + (p_local >> 3), nh = p_local & 7;
            float* st  = scr + pr * 512;
            float* sq  = scr + 1024 + pr * 64;
            float* sa  = scr + 1152 + pr * 64;
            float* qp  = scr + 1280 + pr * 256;
            float* scp = scr + 1792 + pr * 128;
            for (int i = tid2; i < 512; i += 256)
                st[i] = __ldcg(t4 + (i >> 2) * 128 + b * 4 + (i & 3));
            __syncthreads();
            {
                int d = tid2 & 63, kq = tid2 >> 6;
                float a = 0.f;
                const float* wp = WqT + nh * 64 + d;
                int k0 = kq * 128;
#pragma unroll 16
                for (int k = k0; k < k0 + 128; k++) a += st[k] * wp[(size_t)k * 512];
                qp[kq * 64 + d] = a;
            }
            __syncthreads();
            if (tid2 < 64)
                sq[tid2] = bq[nh * 64 + tid2] + qp[tid2] + qp[64 + tid2] + qp[128 + tid2] + qp[192 + tid2];
            __syncthreads();
            if (tid2 < 128) {
                int s = tid2 & 63, dh = tid2 >> 6;
                float a = 0.f;
                const float* kp = keyup + (((size_t)(b * 8 + nh)) * 64 + s) * 64 + dh * 32;
                const float* sqh = sq + dh * 32;
                const float* wwh = Ww + dh * 32;
#pragma unroll 8
                for (int d = 0; d < 32; d++) a += tanhf(sqh[d] + kp[d]) * wwh[d];
                scp[dh * 64 + s] = a;
            }
            __syncthreads();
            if (tid2 < 64) {
                float sc = scp[tid2] + scp[64 + tid2] + bw[0];
                if (mask[b * S_ + tid2]) sc -= 1e9f;
                sa[tid2] = sc;
            }
            __syncthreads();
            if (tid2 < 32) {
                float v0 = sa[tid2], v1 = sa[tid2 + 32];
                float mx = fmaxf(v0, v1);
#pragma unroll
                for (int o = 16; o; o >>= 1) mx = fmaxf(mx, __shfl_xor_sync(0xffffffffu, mx, o));
                float e0 = expf(v0 - mx), e1 = expf(v1 - mx);
                float sum = e0 + e1;
#pragma unroll
                for (int o = 16; o; o >>= 1) sum += __shfl_xor_sync(0xffffffffu, sum, o);
                float inv = 1.f / sum;
                sa[tid2] = e0 * inv;
                sa[tid2 + 32] = e1 * inv;
            }
            __syncthreads();
            if (tid2 < 128) {
                float a = 0.f;
                const float* vp = enc_out + (size_t)b * U_ + nh * 128 + tid2;
#pragma unroll
                for (int s = 0; s < 64; s++) a += sa[s] * vp[(size_t)s * B_ * U_];
                int n = nh * 128 + tid2;
                c4[(n >> 2) * 128 + b * 4 + (n & 3)] = a;
                feat[((size_t)b * T_ + t) * FEATW + 1024 + n] = a;
            }
        }
        {
            h_r = 0.f; h_z = 0.f; h_hn = 0.f;
            const float4* xp = reinterpret_cast<const float4*>(t4) + q * 1024 + b0 + bl;
            const float4* wr4 = reinterpret_cast<const float4*>(W2hs + (jl * 3 + 0) * 512) + q * 32;
            const float4* wz4 = reinterpret_cast<const float4*>(W2hs + (jl * 3 + 1) * 512) + q * 32;
            const float4* wn4 = reinterpret_cast<const float4*>(W2hs + (jl * 3 + 2) * 512) + q * 32;
#pragma unroll 8
            for (int kk = 0; kk < 32; kk++) {
                float4 x = __ldcg(xp + kk * 32);
                float4 wr = wr4[kk], wz = wz4[kk], wn = wn4[kk];
                h_r  += x.x * wr.x + x.y * wr.y + x.z * wr.z + x.w * wr.w;
                h_z  += x.x * wz.x + x.y * wz.y + x.z * wz.z + x.w * wz.w;
                h_hn += x.x * wn.x + x.y * wn.y + x.z * wn.z + x.w * wn.w;
            }
        }
        gsync(gen, ctr);

        // P3
        float a_r = h_r, a_z = h_z, a_xn = 0.f, a_hn = h_hn;
        {
            const float4* xp = reinterpret_cast<const float4*>(c4) + q * 2048 + b0 + bl;
            const float4* wr4 = reinterpret_cast<const float4*>(W2xs + (jl * 3 + 0) * 1024) + q * 64;
            const float4* wz4 = reinterpret_cast<const float4*>(W2xs + (jl * 3 + 1) * 1024) + q * 64;
            const float4* wn4 = reinterpret_cast<const float4*>(W2xs + (jl * 3 + 2) * 1024) + q * 64;
#pragma unroll 8
            for (int kk = 0; kk < 64; kk++) {
                float4 x = __ldcg(xp + kk * 32);
                float4 wr = wr4[kk], wz = wz4[kk], wn = wn4[kk];
                a_r  += x.x * wr.x + x.y * wr.y + x.z * wr.z + x.w * wr.w;
                a_z  += x.x * wz.x + x.y * wz.y + x.z * wz.z + x.w * wz.w;
                a_xn += x.x * wn.x + x.y * wn.y + x.z * wn.z + x.w * wn.w;
            }
            if (q) {
                int o = (q - 1) * 512 + (jl * 16 + bl) * 4;
                scr[o] = a_r; scr[o + 1] = a_z; scr[o + 2] = a_xn; scr[o + 3] = a_hn;
            }
        }
        __syncthreads();
        if (q == 0) {
            int o = (jl * 16 + bl) * 4;
            a_r  += scr[o] + scr[512 + o] + scr[1024 + o];
            a_z  += scr[o + 1] + scr[512 + o + 1] + scr[1024 + o + 1];
            a_xn += scr[o + 2] + scr[512 + o + 2] + scr[1024 + o + 2];
            a_hn += scr[o + 3] + scr[512 + o + 3] + scr[1024 + o + 3];
            int j = j0 + jl, b = b0 + bl, m = b * T_ + t;
            float r = 1.f / (1.f + expf(-(a_r + bfx2[j] + g2bh[j])));
            float z = 1.f / (1.f + expf(-(a_z + bfx2[512 + j] + g2bh[512 + j])));
            float n = tanhf(a_xn + bfx2[1024 + j] + r * (a_hn + g2bh[1024 + j]));
            float hp = __ldcg(t4 + (j >> 2) * 128 + b * 4 + (j & 3));
            float o2 = (1.f - z) * n + z * hp;
            hT4[(j >> 2) * 128 + b * 4 + (j & 3)] = o2;
            feat[(size_t)m * FEATW + 512 + j] = o2;
        }
        gsync(gen, ctr);
    }
}

// ============ bf16 hi/lo split for embed_w ============
__global__ void k_convB(const float* __restrict__ W, __nv_bfloat16* __restrict__ Bp) {
    int idx = blockIdx.x * 256 + threadIdx.x;
    if (idx >= 32000 * 128) return;
    int n = idx >> 7, kg = (idx & 127) << 2;
    float4 v = *reinterpret_cast<const float4*>(W + (size_t)n * 512 + kg);
    __nv_bfloat16 h[4], l[4];
    float x[4] = {v.x, v.y, v.z, v.w};
#pragma unroll
    for (int i = 0; i < 4; i++) {
        h[i] = __float2bfloat16(x[i]);
        l[i] = __float2bfloat16(x[i] - __bfloat162float(h[i]));
    }
    __nv_bfloat162* p0 = reinterpret_cast<__nv_bfloat162*>(Bp + (size_t)n * 1536 + kg);
    __nv_bfloat162* p1 = reinterpret_cast<__nv_bfloat162*>(Bp + (size_t)n * 1536 + 512 + kg);
    __nv_bfloat162* p2 = reinterpret_cast<__nv_bfloat162*>(Bp + (size_t)n * 1536 + 1024 + kg);
    p0[0] = __nv_bfloat162(h[0], h[1]); p0[1] = __nv_bfloat162(h[2], h[3]);
    p1[0] = __nv_bfloat162(l[0], l[1]); p1[1] = __nv_bfloat162(l[2], l[3]);
    p2[0] = __nv_bfloat162(h[0], h[1]); p2[1] = __nv_bfloat162(h[2], h[3]);
}

// ============ HMMA machinery ============
#define HG_A_BYTES 16384
#define HG_B_BYTES 16384
#define HG_SMEM_TOTAL (2 * (HG_A_BYTES + HG_B_BYTES))

#define HLOADG(s, buf, Ag, Bg, LDA) { \
    uint32_t ab_ = sb_a + (buf) * HG_A_BYTES; \
    uint32_t bb_ = sb_b + (buf) * HG_B_BYTES; \
    const __nv_bfloat16* As_ = (Ag) + (s) * 64; \
    const __nv_bfloat16* Bs_ = (Bg) + (s) * 64; \
    _Pragma("unroll") \
    for (int i_ = 0; i_ < 4; i_++) { int ix_ = tid + i_ * 256; int r_ = ix_ >> 3, c_ = ix_ & 7; \
        cp_async16(ab_ + SW128(r_ * 128 + c_ * 16), As_ + (size_t)r_ * (LDA) + c_ * 8); } \
    _Pragma("unroll") \
    for (int i_ = 0; i_ < 4; i_++) { int ix_ = tid + i_ * 256; int r_ = ix_ >> 3, c_ = ix_ & 7; \
        cp_async16(bb_ + SW128(r_ * 128 + c_ * 16), Bs_ + (size_t)r_ * (LDA) + c_ * 8); } \
    CP_COMMIT(); }

#define HMMA_BODY(NSLAB, Ag, Bg, LDA) \
    float acc[2][8][4]; \
    _Pragma("unroll") \
    for (int i = 0; i < 2; i++) \
        _Pragma("unroll") \
        for (int j = 0; j < 8; j++) \
            _Pragma("unroll") \
            for (int v = 0; v < 4; v++) acc[i][j][v] = 0.f; \
    HLOADG(0, 0, Ag, Bg, LDA); \
    HLOADG(1, 1, Ag, Bg, LDA); \
    const int a_row_off = ((lane >> 3) & 1) * 8 + (lane & 7); \
    const int a_kb_off  = ((lane >> 4) & 1) * 16; \
    const int b_row_off = ((lane >> 4) & 1) * 8 + (lane & 7); \
    const int b_kb_off  = ((lane >> 3) & 1) * 16; \
    for (int s = 0; s < (NSLAB); s++) { \
        int buf = s & 1; \
        CP_WAIT(1); \
        __syncthreads(); \
        uint32_t abase = sb_a + buf * HG_A_BYTES; \
        uint32_t bbase = sb_b + buf * HG_B_BYTES; \
        _Pragma("unroll") \
        for (int kk = 0; kk < 4; kk++) { \
            uint32_t a[2][4]; \
            _Pragma("unroll") \
            for (int mi = 0; mi < 2; mi++) { \
                int row = m0 + mi * 16 + a_row_off; \
                int kb = kk * 32 + a_kb_off; \
                ldsm_x4(a[mi][0], a[mi][1], a[mi][2], a[mi][3], abase + SW128(row * 128 + kb)); \
            } \
            uint32_t bfr[4][4]; \
            _Pragma("unroll") \
            for (int ng = 0; ng < 4; ng++) { \
                int row = n0 + ng * 16 + b_row_off; \
                int kb = kk * 32 + b_kb_off; \
                ldsm_x4(bfr[ng][0], bfr[ng][1], bfr[ng][2], bfr[ng][3], bbase + SW128(row * 128 + kb)); \
            } \
            _Pragma("unroll") \
            for (int mi = 0; mi < 2; mi++) \
                _Pragma("unroll") \
                for (int nj = 0; nj < 8; nj++) { \
                    uint32_t b0 = bfr[nj >> 1][(nj & 1) * 2]; \
                    uint32_t b1 = bfr[nj >> 1][(nj & 1) * 2 + 1]; \
                    mma16816(acc[mi][nj][0], acc[mi][nj][1], acc[mi][nj][2], acc[mi][nj][3], \
                             a[mi][0], a[mi][1], a[mi][2], a[mi][3], b0, b1); \
                } \
        } \
        __syncthreads(); \
        if (s + 2 < (NSLAB)) HLOADG(s + 2, buf, Ag, Bg, LDA); \
    }

// final tied projection, K'=1536
__global__ __launch_bounds__(256, 2)
void mma_gemm_hmma(const __nv_bfloat16* __restrict__ Ap, const __nv_bfloat16* __restrict__ Bp,
                   float* __restrict__ C) {
    extern __shared__ char smemc[];
    uint32_t sb_a = smem_to_u32(smemc);
    uint32_t sb_b = sb_a + 2 * HG_A_BYTES;
    const int tid = threadIdx.x, lane = tid & 31, wid = tid >> 5;
    const int mt = blockIdx.y, nt = blockIdx.x;
    const int m0 = (wid & 3) * 32;
    const int n0 = (wid >> 2) * 64;
    const __nv_bfloat16* Ag = Ap + (size_t)mt * 128 * 1536;
    const __nv_bfloat16* Bg = Bp + (size_t)nt * 128 * 1536;

    HMMA_BODY(24, Ag, Bg, 1536)

    int gr = mt * 128 + m0 + (lane >> 2);
    int gc = nt * 128 + n0 + (lane & 3) * 2;
#pragma unroll
    for (int mi = 0; mi < 2; mi++) {
#pragma unroll
        for (int nj = 0; nj < 8; nj++) {
            float* p0 = C + (size_t)(gr + mi * 16) * V_ + gc + nj * 8;
            float* p1 = C + (size_t)(gr + mi * 16 + 8) * V_ + gc + nj * 8;
            *reinterpret_cast<float2*>(p0) = make_float2(acc[mi][nj][0], acc[mi][nj][1]);
            *reinterpret_cast<float2*>(p1) = make_float2(acc[mi][nj][2], acc[mi][nj][3]);
        }
    }
}

// logits HMMA: tanh(featHL @ WopkHL^T + bo2) -> Ahl hi/hi/lo (K'=6144)
__global__ __launch_bounds__(256, 2)
void mma_logits_hmma(const __nv_bfloat16* __restrict__ Ap, const __nv_bfloat16* __restrict__ Bp,
                     const float* __restrict__ bo2, __nv_bfloat16* __restrict__ Ahl) {
    extern __shared__ char smemc[];
    uint32_t sb_a = smem_to_u32(smemc);
    uint32_t sb_b = sb_a + 2 * HG_A_BYTES;
    const int tid = threadIdx.x, lane = tid & 31, wid = tid >> 5;
    const int mt = blockIdx.y, nt = blockIdx.x;
    const int m0 = (wid & 3) * 32;
    const int n0 = (wid >> 2) * 64;
    const __nv_bfloat16* Ag = Ap + (size_t)mt * 128 * 6144;
    const __nv_bfloat16* Bg = Bp + (size_t)nt * 128 * 6144;

    HMMA_BODY(96, Ag, Bg, 6144)

    int gr = mt * 128 + m0 + (lane >> 2);
    int gc = nt * 128 + n0 + (lane & 3) * 2;
#pragma unroll
    for (int mi = 0; mi < 2; mi++) {
#pragma unroll
        for (int half = 0; half < 2; half++) {
            int m = gr + mi * 16 + half * 8;
#pragma unroll
            for (int nj = 0; nj < 8; nj++) {
#pragma unroll
                for (int c = 0; c < 2; c++) {
                    int n = gc + nj * 8 + c;
                    float v = tanhf(acc[mi][nj][half * 2 + c] + bo2[n]);
                    __nv_bfloat16 hi = __float2bfloat16(v);
                    __nv_bfloat16 lo = __float2bfloat16(v - __bfloat162float(hi));
                    Ahl[(size_t)m * 1536 + n] = hi;
                    Ahl[(size_t)m * 1536 + 512 + n] = hi;
                    Ahl[(size_t)m * 1536 + 1024 + n] = lo;
                }
            }
        }
    }
}

// generic prep HMMA: C = A' @ B'^T (+bias); mode 0 plain [m*N+n], 2 keyup remap, 3 X1T remap
__global__ __launch_bounds__(256, 2)
void mma_prep_hmma(const __nv_bfloat16* __restrict__ Ap, const __nv_bfloat16* __restrict__ Bp,
                   const float* __restrict__ bias, float* __restrict__ C,
                   int nslab, int lda, int N, int mode) {
    extern __shared__ char smemc[];
    uint32_t sb_a = smem_to_u32(smemc);
    uint32_t sb_b = sb_a + 2 * HG_A_BYTES;
    const int tid = threadIdx.x, lane = tid & 31, wid = tid >> 5;
    const int mt = blockIdx.y, nt = blockIdx.x;
    const int m0 = (wid & 3) * 32;
    const int n0 = (wid >> 2) * 64;
    const __nv_bfloat16* Ag = Ap + (size_t)mt * 128 * lda;
    const __nv_bfloat16* Bg = Bp + (size_t)nt * 128 * lda;

    HMMA_BODY(nslab, Ag, Bg, lda)

    int gr = mt * 128 + m0 + (lane >> 2);
    int gc = nt * 128 + n0 + (lane & 3) * 2;
#pragma unroll
    for (int mi = 0; mi < 2; mi++) {
#pragma unroll
        for (int half = 0; half < 2; half++) {
            int m = gr + mi * 16 + half * 8;
#pragma unroll
            for (int nj = 0; nj < 8; nj++) {
#pragma unroll
                for (int c = 0; c < 2; c++) {
                    int n = gc + nj * 8 + c;
                    float v = acc[mi][nj][half * 2 + c];
                    if (bias) v += bias[n];
                    if (mode == 2) {
                        int s_ = m >> 5, b_ = m & 31, nh_ = n >> 6, d_ = n & 63;
                        C[(((size_t)(b_ * 8 + nh_) * 64) + s_) * 64 + d_] = v;
                    } else if (mode == 3) {
                        int b_ = m >> 6, t_ = m & 63;
                        C[((size_t)t_ * 1536 + n) * 32 + b_] = v;
                    } else {
                        C[(size_t)m * N + n] = v;
                    }
                }
            }
        }
    }
}

// ---------------- host orchestration ----------------
extern "C" void kernel_launch(void* const* d_in, const int* in_sizes, int n_in,
                              void* d_out, int out_size) {
    const int*   tokens  = (const int*)d_in[0];
    const unsigned char* enc_mask = (const unsigned char*)d_in[1];
    const float* enc_out = (const float*)d_in[2];
    const float* embed_w = (const float*)d_in[3];
    const float* g1Wx = (const float*)d_in[4];
    const float* g1Wh = (const float*)d_in[5];
    const float* g1bx = (const float*)d_in[6];
    const float* g1bh = (const float*)d_in[7];
    const float* g2Wx = (const float*)d_in[8];
    const float* g2Wh = (const float*)d_in[9];
    const float* g2bx = (const float*)d_in[10];
    const float* g2bh = (const float*)d_in[11];
    const float* brW  = (const float*)d_in[12];
    const float* brB  = (const float*)d_in[13];
    const float* Wk   = (const float*)d_in[14];
    const float* bk   = (const float*)d_in[15];
    const float* Wq   = (const float*)d_in[16];
    const float* bq   = (const float*)d_in[17];
    const float* Ww   = (const float*)d_in[18];
    const float* bw   = (const float*)d_in[19];
    const float* Wf   = (const float*)d_in[20];
    const float* bf   = (const float*)d_in[21];
    const float* Wo   = (const float*)d_in[22];
    const float* bo   = (const float*)d_in[23];
    float* out = (float*)d_out;

    float* S = nullptr;
    cudaGetSymbolAddress((void**)&S, g_scratch);
    float* feat    = S + OFF_FEAT;
    float* keyup   = S + OFF_KEYUP;
    float* hT4     = S + OFF_HT;
    float* t4      = S + OFF_TMP;
    float* c4      = S + OFF_CTXRT;
    float* X1T     = S + OFF_X1ALL;
    float* Wfx2    = S + OFF_WFX2;
    float* bfx2    = S + OFF_BFX2;
    float* WqT     = S + OFF_WQT;
    float* WfT     = S + OFF_WFT;
    float* Wo2f    = S + OFF_WO2F;
    float* Wopk    = S + OFF_WOPK;
    float* bo2     = S + OFF_BO2;
    __nv_bfloat16* Ahl   = (__nv_bfloat16*)(S + OFF_AHL);
    __nv_bfloat16* Bhl   = (__nv_bfloat16*)(S + OFF_BHL);
    __nv_bfloat16* Fhl   = (__nv_bfloat16*)(S + OFF_FHL);
    __nv_bfloat16* Wohl  = (__nv_bfloat16*)(S + OFF_WOHL);
    __nv_bfloat16* EncHL = (__nv_bfloat16*)(S + OFF_ENCHL);
    __nv_bfloat16* WkHL  = (__nv_bfloat16*)(S + OFF_WKHL);
    __nv_bfloat16* EmbHL = (__nv_bfloat16*)(S + OFF_EMBHL);
    __nv_bfloat16* G1xHL = (__nv_bfloat16*)(S + OFF_G1WXHL);
    __nv_bfloat16* G2xHL = (__nv_bfloat16*)(S + OFF_G2WXHL);
    __nv_bfloat16* WfTHL = (__nv_bfloat16*)(S + OFF_WFTHL);
    __nv_bfloat16* WoAHL = (__nv_bfloat16*)(S + OFF_WOAHL);

    // ---- prep ----
    k_embed<<<B_ * T_, 128>>>(tokens, embed_w, feat);
    k_bridge<<<B_, 512>>>(enc_mask, enc_out, brW, brB, hT4);
    k_transpose<<<(512 * 512 + 255) / 256, 256>>>(Wq, WqT, 512, 512);
    k_transpose<<<(1024 * 1024 + 255) / 256, 256>>>(Wf, WfT, 1024, 1024);
    k_bfx2<<<192, 256>>>(g2Wx, bf, g2bx, bfx2);
    k_bo2<<<64, 256>>>(Wo, bf, bo, bo2);
    k_convB<<<(32000 * 128 + 255) / 256, 256>>>(embed_w, Bhl);

    // hi/lo conversions for prep GEMM operands
    k_convHLG<<<(2048 * 256 + 255) / 256, 256>>>(enc_out, EncHL, 2048, 1024, 1024, 0);
    k_convHLG<<<(512 * 256 + 255) / 256, 256>>>(Wk, WkHL, 512, 1024, 1024, 1);
    k_convHLG<<<(2048 * 128 + 255) / 256, 256>>>(feat, EmbHL, 2048, 512, 2048, 0);
    k_convHLG<<<(1536 * 128 + 255) / 256, 256>>>(g1Wx, G1xHL, 1536, 512, 512, 1);
    k_convHLG<<<(1536 * 256 + 255) / 256, 256>>>(g2Wx, G2xHL, 1536, 1024, 1024, 0);
    k_convHLG<<<(1024 * 256 + 255) / 256, 256>>>(WfT, WfTHL, 1024, 1024, 1024, 1);
    k_convHLG<<<(512 * 256 + 255) / 256, 256>>>(Wo + 1024, WoAHL, 512, 1024, 2048, 0);

    cudaFuncSetAttribute(mma_prep_hmma, cudaFuncAttributeMaxDynamicSharedMemorySize, HG_SMEM_TOTAL);
    {   // keyup = enc @ Wk^T + bk (mode 2 remap)
        dim3 g(4, 16);
        mma_prep_hmma<<<g, 256, HG_SMEM_TOTAL>>>(EncHL, WkHL, bk, keyup, 48, 3072, 512, 2);
    }
    {   // X1T = emb @ g1Wx^T + g1bx (mode 3 remap)
        dim3 g(12, 16);
        mma_prep_hmma<<<g, 256, HG_SMEM_TOTAL>>>(EmbHL, G1xHL, g1bx, X1T, 24, 1536, 1536, 3);
    }
    {   // Wfx2 = g2Wx (x) Wf
        dim3 g(8, 12);
        mma_prep_hmma<<<g, 256, HG_SMEM_TOTAL>>>(G2xHL, WfTHL, nullptr, Wfx2, 48, 3072, 1024, 0);
    }
    {   // Wo2f
        dim3 g(8, 4);
        mma_prep_hmma<<<g, 256, HG_SMEM_TOTAL>>>(WoAHL, WfTHL, nullptr, Wo2f, 48, 3072, 1024, 0);
    }
    k_wopack<<<(512 * 2048 + 255) / 256, 256>>>(Wo, Wo2f, Wopk);
    k_convHL<<<(512 * 512 + 255) / 256, 256>>>(Wopk, Wohl, 512, 1);

    // ---- persistent recurrence ----
    k_zero<<<1, 1>>>();
    cudaFuncSetAttribute(k_persistent, cudaFuncAttributeMaxDynamicSharedMemorySize, PERS_SMEM);
    k_persistent<<<NB, 512, PERS_SMEM>>>(X1T, g1Wh, g1bh, Wfx2, bfx2, g2Wh, g2bh,
                                         WqT, bq, Ww, bw,
                                         enc_out, enc_mask, keyup,
                                         feat, hT4, t4, c4);

    // ---- tail ----
    k_convHL<<<(2048 * 512 + 255) / 256, 256>>>(feat, Fhl, 2048, 0);
    cudaFuncSetAttribute(mma_logits_hmma, cudaFuncAttributeMaxDynamicSharedMemorySize, HG_SMEM_TOTAL);
    {
        dim3 g(4, 16);
        mma_logits_hmma<<<g, 256, HG_SMEM_TOTAL>>>(Fhl, Wohl, bo2, Ahl);
    }
    cudaFuncSetAttribute(mma_gemm_hmma, cudaFuncAttributeMaxDynamicSharedMemorySize, HG_SMEM_TOTAL);
    {
        dim3 g(V_ / 128, 2048 / 128);
        mma_gemm_hmma<<<g, 256, HG_SMEM_TOTAL>>>(Ahl, Bhl, out);
    }
}